// round 11
// baseline (speedup 1.0000x reference)
#include <cuda_runtime.h>
#include <cuda_fp16.h>
#include <cstdint>

// ---------------- problem constants ----------------
#define B_    8
#define NTOK  4096
#define C_    768
#define H_    12
#define D_    64
#define M_    (B_ * NTOK)     // 32768
#define QKVN  (3 * C_)        // 2304
#define KDIM  768

// ---------------- scratch (device globals) ----------------
__device__ __half g_phiq[(size_t)B_ * H_ * NTOK * D_];
__device__ __half g_phik[(size_t)B_ * H_ * NTOK * D_];
__device__ __half g_v   [(size_t)B_ * H_ * NTOK * D_];
__device__ __half g_kvT [B_ * H_ * D_ * D_];         // [bh][e][d]
__device__ float  g_ksum[B_ * H_ * D_];
__device__ __half g_attn[(size_t)M_ * C_];

__device__ __half g_xh [(size_t)M_ * KDIM];
__device__ __half g_w  [(size_t)QKVN * KDIM];
__device__ __half g_pw [(size_t)C_ * KDIM];
__device__ __half g_lh [(size_t)M_ * KDIM];

// ---------------- low-level helpers ----------------
__device__ __forceinline__ uint32_t smem_to_u32(const void* p) {
    uint32_t a;
    asm("{ .reg .u64 t; cvta.to.shared.u64 t, %1; cvt.u32.u64 %0, t; }"
        : "=r"(a) : "l"(p));
    return a;
}

#define CP_ASYNC_CG(dst, src) \
    asm volatile("cp.async.cg.shared.global [%0], [%1], 16;" :: "r"(dst), "l"(src))
#define CP_COMMIT()  asm volatile("cp.async.commit_group;" ::: "memory")
#define CP_WAIT(N)   asm volatile("cp.async.wait_group %0;" :: "n"(N) : "memory")

#define LDMATRIX_X4(r0, r1, r2, r3, addr) \
    asm volatile("ldmatrix.sync.aligned.m8n8.x4.shared.b16 {%0,%1,%2,%3}, [%4];" \
        : "=r"(r0), "=r"(r1), "=r"(r2), "=r"(r3) : "r"(addr))
#define LDMATRIX_X2(r0, r1, addr) \
    asm volatile("ldmatrix.sync.aligned.m8n8.x2.shared.b16 {%0,%1}, [%2];" \
        : "=r"(r0), "=r"(r1) : "r"(addr))
#define LDMATRIX_X4_T(r0, r1, r2, r3, addr) \
    asm volatile("ldmatrix.sync.aligned.m8n8.x4.trans.shared.b16 {%0,%1,%2,%3}, [%4];" \
        : "=r"(r0), "=r"(r1), "=r"(r2), "=r"(r3) : "r"(addr))
#define LDMATRIX_X2_T(r0, r1, addr) \
    asm volatile("ldmatrix.sync.aligned.m8n8.x2.trans.shared.b16 {%0,%1}, [%2];" \
        : "=r"(r0), "=r"(r1) : "r"(addr))

#define MMA_F16(d, a, b) \
    asm volatile("mma.sync.aligned.m16n8k16.row.col.f32.f16.f16.f32 " \
        "{%0,%1,%2,%3}, {%4,%5,%6,%7}, {%8,%9}, {%0,%1,%2,%3};" \
        : "+f"((d)[0]), "+f"((d)[1]), "+f"((d)[2]), "+f"((d)[3]) \
        : "r"((a)[0]), "r"((a)[1]), "r"((a)[2]), "r"((a)[3]), \
          "r"((b)[0]), "r"((b)[1]))

// ---------------- GEMM tiling: 8 warps of 64x32; BKB=64, 2 stages ----------
#define BM 128
#define BN 128
#define BKB 64                    // f16 k-elems per stage
#define KB  (KDIM / BKB)          // 12 k-blocks
#define ROWB 144                  // bytes per 64-half row (128B data + 16B pad)
#define ARR_BYTES (128 * ROWB)    // 18432
#define STAGE (2 * ARR_BYTES)     // 36864
#define NSTG 2
#define SMEM_GEMM (NSTG * STAGE)  // 73728

__device__ __forceinline__ void gemm_mainloop(
    const __half* __restrict__ A, const __half* __restrict__ Bw,
    int bm, int bn, uint32_t sb, int tid, int wid, int lane,
    float acc[4][4][4])
{
    const int wm = (wid & 1) * 64;
    const int wn = (wid >> 1) * 32;

    // fill: each thread owns one 128B row (A for tid<128, B for tid>=128)
    const int farr = tid >> 7;           // 0 = A, 1 = B
    const int frow = tid & 127;
    const __half* fsrc = (farr ? Bw : A) + (size_t)((farr ? bn : bm) + frow) * KDIM;
    const uint32_t fdst = sb + (uint32_t)(farr * ARR_BYTES + frow * ROWB);

    const uint32_t a_row  = (uint32_t)(wm + (lane & 15));
    const uint32_t a_colb = (uint32_t)(((lane >> 4) & 1) * 16);
    const uint32_t b_row  = (uint32_t)(wn + (lane & 7));
    const uint32_t b_colb = (uint32_t)(((lane >> 3) & 1) * 16);

    #pragma unroll
    for (int i = 0; i < 4; i++)
        #pragma unroll
        for (int j = 0; j < 4; j++)
            #pragma unroll
            for (int r = 0; r < 4; r++) acc[i][j][r] = 0.f;

    // preload stage 0
    {
        #pragma unroll
        for (int ch = 0; ch < 8; ch++)
            CP_ASYNC_CG(fdst + ch * 16, fsrc + ch * 8);
        CP_COMMIT();
    }

    for (int kb = 0; kb < KB; kb++) {
        CP_WAIT(0);                 // stage kb's fill complete
        __syncthreads();            // visible to all; all warps done with kb-1

        if (kb + 1 < KB) {          // fill other slot (safe: barrier above)
            const uint32_t so = (uint32_t)(((kb + 1) & 1) * STAGE);
            const int k0 = (kb + 1) * BKB;
            #pragma unroll
            for (int ch = 0; ch < 8; ch++)
                CP_ASYNC_CG(fdst + so + ch * 16, fsrc + k0 + ch * 8);
            CP_COMMIT();
        }

        const uint32_t st = sb + (uint32_t)((kb & 1) * STAGE);
        #pragma unroll
        for (int ks = 0; ks < 4; ks++) {
            const uint32_t kB = (uint32_t)(ks * 32);   // 16 halfs = 32 B
            uint32_t af[4][4], bf[4][2];
            #pragma unroll
            for (int mt = 0; mt < 4; mt++) {
                uint32_t ao = st + (a_row + mt * 16) * ROWB + kB + a_colb;
                LDMATRIX_X4(af[mt][0], af[mt][1], af[mt][2], af[mt][3], ao);
            }
            #pragma unroll
            for (int nt = 0; nt < 4; nt++) {
                uint32_t bo = st + ARR_BYTES + (b_row + nt * 8) * ROWB + kB + b_colb;
                LDMATRIX_X2(bf[nt][0], bf[nt][1], bo);
            }
            #pragma unroll
            for (int mt = 0; mt < 4; mt++)
                #pragma unroll
                for (int nt = 0; nt < 4; nt++)
                    MMA_F16(acc[mt][nt], af[mt], bf[nt]);
        }
    }
}

// ---------------- GEMM1: qkv with fused bias+rope+softmax+scatter ----------
#define EPS 132

__global__ __launch_bounds__(256, 2)
void mma_gemm_qkv(const __half* __restrict__ A, const __half* __restrict__ Bw,
                  const float* __restrict__ rope,
                  const float* __restrict__ q_bias, const float* __restrict__ v_bias,
                  __half* __restrict__ phiq, __half* __restrict__ phik, __half* __restrict__ vout)
{
    extern __shared__ char smem[];
    const uint32_t sb = smem_to_u32(smem);
    const int tid = threadIdx.x, wid = tid >> 5, lane = tid & 31;
    const int bm = blockIdx.y * BM, bn = blockIdx.x * BN;

    float acc[4][4][4];
    gemm_mainloop(A, Bw, bm, bn, sb, tid, wid, lane, acc);
    __syncthreads();

    float* epi = (float*)smem;   // 128x128 @ stride 132 = 67584 B < 73728
    const int wm = (wid & 1) * 64, wn = (wid >> 1) * 32;
    const int er = lane >> 2, ec = (lane & 3) * 2;
    #pragma unroll
    for (int mt = 0; mt < 4; mt++)
        #pragma unroll
        for (int nt = 0; nt < 4; nt++) {
            int r0 = wm + mt * 16 + er, c = wn + nt * 8 + ec;
            *(float2*)&epi[r0 * EPS + c]       = make_float2(acc[mt][nt][0], acc[mt][nt][1]);
            *(float2*)&epi[(r0 + 8) * EPS + c] = make_float2(acc[mt][nt][2], acc[mt][nt][3]);
        }
    __syncthreads();

    const int region = bn / C_;
    const int col0   = bn - region * C_;
    const float* bias = (region == 0) ? q_bias : (region == 2 ? v_bias : nullptr);
    __half* outbuf = (region == 0) ? phiq : (region == 1 ? phik : vout);

    const int sub    = lane >> 4;
    const int lane15 = lane & 15;
    const int g      = lane15 >> 3;
    const int dof    = (lane15 & 7) << 3;
    const int h      = (col0 >> 6) + g;

    #pragma unroll 2
    for (int rr = 0; rr < 8; rr++) {
        const int row  = wid * 16 + rr * 2 + sub;
        const int gtok = bm + row;
        const int b    = gtok >> 12;
        const int n    = gtok & (NTOK - 1);

        float4 v0 = *(float4*)&epi[row * EPS + g * 64 + dof];
        float4 v1 = *(float4*)&epi[row * EPS + g * 64 + dof + 4];
        float vals[8] = { v0.x, v0.y, v0.z, v0.w, v1.x, v1.y, v1.z, v1.w };

        if (bias) {
            #pragma unroll
            for (int j = 0; j < 8; j++) vals[j] += bias[col0 + g * 64 + dof + j];
        }

        if (region != 2) {
            if (n >= 1) {
                const float* rp = rope + (size_t)(n - 1) * (2 * D_) + dof;
                float4 s0 = *(const float4*)rp;
                float4 s1 = *(const float4*)(rp + 4);
                float4 c0 = *(const float4*)(rp + 64);
                float4 c1 = *(const float4*)(rp + 68);
                float snv[8] = { s0.x, s0.y, s0.z, s0.w, s1.x, s1.y, s1.z, s1.w };
                float csv[8] = { c0.x, c0.y, c0.z, c0.w, c1.x, c1.y, c1.z, c1.w };
                #pragma unroll
                for (int p = 0; p < 4; p++) {
                    float t0 = vals[2 * p], t1 = vals[2 * p + 1];
                    vals[2 * p]     = t0 * csv[2 * p]     - t1 * snv[2 * p];
                    vals[2 * p + 1] = t1 * csv[2 * p + 1] + t0 * snv[2 * p + 1];
                }
            }
            float m = vals[0];
            #pragma unroll
            for (int j = 1; j < 8; j++) m = fmaxf(m, vals[j]);
            #pragma unroll
            for (int o = 1; o < 8; o <<= 1)
                m = fmaxf(m, __shfl_xor_sync(0xffffffffu, m, o));
            float s = 0.f;
            #pragma unroll
            for (int j = 0; j < 8; j++) { vals[j] = expf(vals[j] - m); s += vals[j]; }
            #pragma unroll
            for (int o = 1; o < 8; o <<= 1)
                s += __shfl_xor_sync(0xffffffffu, s, o);
            float rs = 1.f / s;
            #pragma unroll
            for (int j = 0; j < 8; j++) vals[j] *= rs;
        }

        __half hv[8];
        #pragma unroll
        for (int j = 0; j < 8; j++) hv[j] = __float2half(vals[j]);
        __half* dst = outbuf + (((size_t)b * H_ + h) * NTOK + n) * D_ + dof;
        *(uint4*)dst = *(uint4*)hv;
    }
}

// ---------------- GEMM2: proj with bias ----------------
__global__ __launch_bounds__(256, 2)
void mma_gemm_proj(const __half* __restrict__ A, const __half* __restrict__ Bw,
                   float* __restrict__ Cc, int N, const float* __restrict__ bias_full)
{
    extern __shared__ char smem[];
    const uint32_t sb = smem_to_u32(smem);
    const int tid = threadIdx.x, wid = tid >> 5, lane = tid & 31;
    const int bm = blockIdx.y * BM, bn = blockIdx.x * BN;

    float acc[4][4][4];
    gemm_mainloop(A, Bw, bm, bn, sb, tid, wid, lane, acc);

    const int wm = (wid & 1) * 64, wn = (wid >> 1) * 32;
    const int er = lane >> 2, ec = (lane & 3) * 2;
    #pragma unroll
    for (int mt = 0; mt < 4; mt++) {
        #pragma unroll
        for (int nt = 0; nt < 4; nt++) {
            int row = bm + wm + mt * 16 + er;
            int col = bn + wn + nt * 8 + ec;
            float b0 = bias_full[col], b1 = bias_full[col + 1];
            *(float2*)(Cc + (size_t)row * N + col) =
                make_float2(acc[mt][nt][0] + b0, acc[mt][nt][1] + b1);
            *(float2*)(Cc + (size_t)(row + 8) * N + col) =
                make_float2(acc[mt][nt][2] + b0, acc[mt][nt][3] + b1);
        }
    }
}

// ---------------- kv via mma (unchanged from R10) ----------------
#define KROWB 144
#define KARR  (64 * KROWB)
#define KSTG  (2 * KARR)

__global__ __launch_bounds__(128)
void kv_mma_kernel(const __half* __restrict__ phik, const __half* __restrict__ v,
                   __half* __restrict__ kvT, float* __restrict__ ksum)
{
    __shared__ char skv[2 * KSTG];
    __shared__ float sred[2][64];
    const uint32_t sb = smem_to_u32(skv);
    const int tid = threadIdx.x, wid = tid >> 5, lane = tid & 31;
    const int bh = blockIdx.x;

    const __half* pk = phik + (size_t)bh * NTOK * D_;
    const __half* pv = v    + (size_t)bh * NTOK * D_;

    const int wd = wid & 1, we = wid >> 1;

    const int akk = (lane & 7) + ((lane >> 4) & 1) * 8;
    const int amm = ((lane >> 3) & 1) * 8;
    const int bkk = (lane & 7) + ((lane >> 3) & 1) * 8;

    float acc[2][4][4];
    #pragma unroll
    for (int i = 0; i < 2; i++)
        #pragma unroll
        for (int j = 0; j < 4; j++)
            #pragma unroll
            for (int r = 0; r < 4; r++) acc[i][j][r] = 0.f;

    float ksl = 0.f;
    const int dloc = tid & 63, rg = tid >> 6;

    auto fill = [&](int kb, int slot) {
        const int n0 = kb * 64;
        const uint32_t so = sb + (uint32_t)(slot * KSTG);
        #pragma unroll
        for (int i = tid; i < 1024; i += 128) {
            int arr = i >> 9;
            int r   = (i >> 3) & 63;
            int ch  = i & 7;
            const __half* src = (arr ? pv : pk) + (size_t)(n0 + r) * D_ + ch * 8;
            CP_ASYNC_CG(so + arr * KARR + r * KROWB + ch * 16, src);
        }
    };

    fill(0, 0); CP_COMMIT();

    for (int kb = 0; kb < NTOK / 64; kb++) {
        __syncthreads();
        if (kb + 1 < NTOK / 64) { fill(kb + 1, (kb + 1) & 1); CP_COMMIT(); CP_WAIT(1); }
        else                    { CP_WAIT(0); }
        __syncthreads();

        const uint32_t st = sb + (uint32_t)((kb & 1) * KSTG);

        const __half* ph = (const __half*)(skv + (kb & 1) * KSTG);
        #pragma unroll 8
        for (int r = rg * 32; r < rg * 32 + 32; r++)
            ksl += __half2float(*(const __half*)((const char*)ph + r * KROWB + dloc * 2));

        #pragma unroll
        for (int ks = 0; ks < 4; ks++) {
            const int k0 = ks * 16;
            uint32_t af[2][4], bf[4][2];
            #pragma unroll
            for (int mt = 0; mt < 2; mt++) {
                uint32_t ao = st + (k0 + akk) * KROWB + (wd * 32 + mt * 16 + amm) * 2;
                LDMATRIX_X4_T(af[mt][0], af[mt][1], af[mt][2], af[mt][3], ao);
            }
            #pragma unroll
            for (int nt = 0; nt < 4; nt++) {
                uint32_t bo = st + KARR + (k0 + bkk) * KROWB + (we * 32 + nt * 8) * 2;
                LDMATRIX_X2_T(bf[nt][0], bf[nt][1], bo);
            }
            #pragma unroll
            for (int mt = 0; mt < 2; mt++)
                #pragma unroll
                for (int nt = 0; nt < 4; nt++)
                    MMA_F16(acc[mt][nt], af[mt], bf[nt]);
        }
    }

    const int er = lane >> 2, ec = (lane & 3) * 2;
    __half* kvb = kvT + (size_t)bh * D_ * D_;
    #pragma unroll
    for (int mt = 0; mt < 2; mt++)
        #pragma unroll
        for (int nt = 0; nt < 4; nt++) {
            int d = wd * 32 + mt * 16 + er;
            int e = we * 32 + nt * 8 + ec;
            kvb[(e)     * D_ + d]     = __float2half(acc[mt][nt][0]);
            kvb[(e + 1) * D_ + d]     = __float2half(acc[mt][nt][1]);
            kvb[(e)     * D_ + d + 8] = __float2half(acc[mt][nt][2]);
            kvb[(e + 1) * D_ + d + 8] = __float2half(acc[mt][nt][3]);
        }

    sred[rg][dloc] = ksl;
    __syncthreads();
    if (rg == 0) ksum[bh * D_ + dloc] = sred[0][dloc] + sred[1][dloc];
}

// ---------------- attn via mma (unchanged from R10) ----------------
__global__ __launch_bounds__(256)
void attn_mma_kernel(const __half* __restrict__ phiq, const __half* __restrict__ kvT,
                     const float* __restrict__ ksum, __half* __restrict__ attn)
{
    __shared__ __half phq[128 * 72];
    __shared__ __half kvt[64 * 72];
    __shared__ float ksm[64];
    __shared__ float zpart[128][2];
    __shared__ float zb[128];

    const int tid = threadIdx.x, wid = tid >> 5, lane = tid & 31;
    const int bh = blockIdx.x;
    const int n0 = blockIdx.y * 128;
    const int b = bh / H_, h = bh % H_;

    const __half* pq = phiq + ((size_t)bh * NTOK + n0) * D_;
    const __half* kb = kvT + (size_t)bh * D_ * D_;

    #pragma unroll
    for (int i = tid; i < 1024; i += 256) {
        int r = i >> 3, ch = i & 7;
        *(uint4*)&phq[r * 72 + ch * 8] = *(const uint4*)(pq + (size_t)r * D_ + ch * 8);
    }
    #pragma unroll
    for (int i = tid; i < 512; i += 256) {
        int r = i >> 3, ch = i & 7;
        *(uint4*)&kvt[r * 72 + ch * 8] = *(const uint4*)(kb + (size_t)r * D_ + ch * 8);
    }
    if (tid < 64) ksm[tid] = ksum[bh * D_ + tid];
    __syncthreads();

    {
        int row = tid >> 1, hh = tid & 1;
        float z = 0.f;
        #pragma unroll 8
        for (int d = hh * 32; d < hh * 32 + 32; d++)
            z += __half2float(phq[row * 72 + d]) * ksm[d];
        zpart[row][hh] = z;
    }
    __syncthreads();
    if (tid < 128) zb[tid] = 1.f / (zpart[tid][0] + zpart[tid][1] + 1e-5f);

    const int wm2 = (wid & 3) * 32, wn2 = (wid >> 2) * 32;
    const uint32_t pq32 = smem_to_u32(phq), kv32 = smem_to_u32(kvt);
    float acc[2][4][4];
    #pragma unroll
    for (int i = 0; i < 2; i++)
        #pragma unroll
        for (int j = 0; j < 4; j++)
            #pragma unroll
            for (int r = 0; r < 4; r++) acc[i][j][r] = 0.f;

    #pragma unroll
    for (int ks = 0; ks < 4; ks++) {
        const int k0 = ks * 16;
        uint32_t af[2][4], bf[4][2];
        #pragma unroll
        for (int mt = 0; mt < 2; mt++) {
            uint32_t ao = pq32 + (wm2 + mt * 16 + (lane & 15)) * 144 + (k0 + ((lane >> 4) & 1) * 8) * 2;
            LDMATRIX_X4(af[mt][0], af[mt][1], af[mt][2], af[mt][3], ao);
        }
        #pragma unroll
        for (int nt = 0; nt < 4; nt++) {
            uint32_t bo = kv32 + (wn2 + nt * 8 + (lane & 7)) * 144 + (k0 + ((lane >> 3) & 1) * 8) * 2;
            LDMATRIX_X2(bf[nt][0], bf[nt][1], bo);
        }
        #pragma unroll
        for (int mt = 0; mt < 2; mt++)
            #pragma unroll
            for (int nt = 0; nt < 4; nt++)
                MMA_F16(acc[mt][nt], af[mt], bf[nt]);
    }
    __syncthreads();

    const int er = lane >> 2, ec = (lane & 3) * 2;
    #pragma unroll
    for (int mt = 0; mt < 2; mt++)
        #pragma unroll
        for (int nt = 0; nt < 4; nt++) {
            int row = wm2 + mt * 16 + er;
            int e   = wn2 + nt * 8 + ec;
            float rz0 = zb[row], rz1 = zb[row + 8];
            size_t base0 = ((size_t)(b * NTOK + n0 + row)) * C_ + h * D_ + e;
            size_t base1 = ((size_t)(b * NTOK + n0 + row + 8)) * C_ + h * D_ + e;
            __half2 o0 = __floats2half2_rn(acc[mt][nt][0] * rz0, acc[mt][nt][1] * rz0);
            __half2 o1 = __floats2half2_rn(acc[mt][nt][2] * rz1, acc[mt][nt][3] * rz1);
            *(__half2*)(attn + base0) = o0;
            *(__half2*)(attn + base1) = o1;
        }
}

// ---------------- fp32 -> fp16 ----------------
__global__ void cvt_h(const float* __restrict__ x, __half* __restrict__ y, int n4)
{
    int i = blockIdx.x * blockDim.x + threadIdx.x;
    if (i >= n4) return;
    float4 f = ((const float4*)x)[i];
    __half h[4];
    h[0] = __float2half(f.x); h[1] = __float2half(f.y);
    h[2] = __float2half(f.z); h[3] = __float2half(f.w);
    ((uint2*)y)[i] = *(uint2*)h;
}

// ---------------- layernorm (fp16 in) -> fp16 --------------------------------
__global__ void ln_kernel(const __half* __restrict__ x,
                          const float* __restrict__ g,
                          const float* __restrict__ b,
                          __half* __restrict__ yh)
{
    int row = blockIdx.x;
    int tid = threadIdx.x; // 256
    const __half* xr = x + (size_t)row * C_;

    float v0 = __half2float(xr[tid]);
    float v1 = __half2float(xr[tid + 256]);
    float v2 = __half2float(xr[tid + 512]);
    float s  = v0 + v1 + v2;
    float ss = v0 * v0 + v1 * v1 + v2 * v2;
#pragma unroll
    for (int o = 16; o > 0; o >>= 1) {
        s  += __shfl_xor_sync(0xffffffffu, s,  o);
        ss += __shfl_xor_sync(0xffffffffu, ss, o);
    }
    __shared__ float ws[8], wss[8];
    int warp = tid >> 5, lane = tid & 31;
    if (lane == 0) { ws[warp] = s; wss[warp] = ss; }
    __syncthreads();
    if (tid == 0) {
        float ts = 0.f, tss = 0.f;
#pragma unroll
        for (int i = 0; i < 8; i++) { ts += ws[i]; tss += wss[i]; }
        ws[0] = ts; wss[0] = tss;
    }
    __syncthreads();
    float mean = ws[0] * (1.f / C_);
    float var  = wss[0] * (1.f / C_) - mean * mean;
    float inv  = rsqrtf(var + 1e-5f);

    size_t rb = (size_t)row * C_;
#pragma unroll
    for (int j = 0; j < 3; j++) {
        int c = tid + j * 256;
        float vv = (j == 0 ? v0 : (j == 1 ? v1 : v2));
        float y = (vv - mean) * inv * g[c] + b[c];
        yh[rb + c] = __float2half(y);
    }
}

// ---------------- launch ------------------------------------------------------
extern "C" void kernel_launch(void* const* d_in, const int* in_sizes, int n_in,
                              void* d_out, int out_size)
{
    (void)in_sizes; (void)n_in; (void)out_size;
    const float* x      = (const float*)d_in[0];
    const float* rope   = (const float*)d_in[1];
    const float* qkv_w  = (const float*)d_in[2];
    const float* q_bias = (const float*)d_in[3];
    const float* v_bias = (const float*)d_in[4];
    const float* norm_g = (const float*)d_in[5];
    const float* norm_b = (const float*)d_in[6];
    const float* proj_w = (const float*)d_in[7];
    const float* proj_b = (const float*)d_in[8];
    float* out = (float*)d_out;

    float *ksum;
    __half *phiq, *phik, *v, *kvT, *attn, *xh, *w, *pw, *lh;
    cudaGetSymbolAddress((void**)&phiq, g_phiq);
    cudaGetSymbolAddress((void**)&phik, g_phik);
    cudaGetSymbolAddress((void**)&v,    g_v);
    cudaGetSymbolAddress((void**)&kvT,  g_kvT);
    cudaGetSymbolAddress((void**)&ksum, g_ksum);
    cudaGetSymbolAddress((void**)&attn, g_attn);
    cudaGetSymbolAddress((void**)&xh,   g_xh);
    cudaGetSymbolAddress((void**)&w,    g_w);
    cudaGetSymbolAddress((void**)&pw,   g_pw);
    cudaGetSymbolAddress((void**)&lh,   g_lh);

    cudaFuncSetAttribute(mma_gemm_qkv,  cudaFuncAttributeMaxDynamicSharedMemorySize, SMEM_GEMM);
    cudaFuncSetAttribute(mma_gemm_proj, cudaFuncAttributeMaxDynamicSharedMemorySize, SMEM_GEMM);

    // 0) conversions
    {
        int n4 = (M_ * KDIM) / 4;
        cvt_h<<<(n4 + 255) / 256, 256>>>(x, xh, n4);
        n4 = (QKVN * KDIM) / 4;
        cvt_h<<<(n4 + 255) / 256, 256>>>(qkv_w, w, n4);
        n4 = (C_ * KDIM) / 4;
        cvt_h<<<(n4 + 255) / 256, 256>>>(proj_w, pw, n4);
    }

    // 1) fused qkv GEMM + bias + rope + softmax + head-scatter (fp16 out)
    mma_gemm_qkv<<<dim3(QKVN / BN, M_ / BM), 256, SMEM_GEMM>>>(
        xh, w, rope, q_bias, v_bias, phiq, phik, v);

    // 2) kv + ksum via tensor cores
    kv_mma_kernel<<<B_ * H_, 128>>>(phik, v, kvT, ksum);

    // 3) attention output via tensor cores
    attn_mma_kernel<<<dim3(B_ * H_, NTOK / 128), 256>>>(phiq, kvT, ksum, attn);

    // 4) layernorm (fp16 -> fp16)
    ln_kernel<<<M_, 256>>>(attn, norm_g, norm_b, lh);

    // 5) out = ln @ proj_w^T + proj_b
    mma_gemm_proj<<<dim3(C_ / BN, M_ / BM), 256, SMEM_GEMM>>>(
        lh, pw, out, C_, proj_b);
}

// round 12
// speedup vs baseline: 1.4922x; 1.4922x over previous
#include <cuda_runtime.h>
#include <cuda_fp16.h>
#include <cstdint>

// ---------------- problem constants ----------------
#define B_    8
#define NTOK  4096
#define C_    768
#define H_    12
#define D_    64
#define M_    (B_ * NTOK)     // 32768
#define QKVN  (3 * C_)        // 2304
#define KDIM  768
#define KVSEG 4               // kv split segments

// ---------------- scratch (device globals) ----------------
__device__ __half g_phiq[(size_t)B_ * H_ * NTOK * D_];
__device__ __half g_phik[(size_t)B_ * H_ * NTOK * D_];
__device__ __half g_v   [(size_t)B_ * H_ * NTOK * D_];
__device__ __half g_kvT [B_ * H_ * D_ * D_];          // [bh][e][d]
__device__ float  g_kvp [KVSEG * B_ * H_ * D_ * D_];  // fp32 partials
__device__ float  g_ksum[B_ * H_ * D_];
__device__ float  g_ksp [KVSEG * B_ * H_ * D_];
__device__ __half g_attn[(size_t)M_ * C_];

__device__ __half g_xh [(size_t)M_ * KDIM];
__device__ __half g_w  [(size_t)QKVN * KDIM];
__device__ __half g_pw [(size_t)C_ * KDIM];
__device__ __half g_lh [(size_t)M_ * KDIM];

// ---------------- low-level helpers ----------------
__device__ __forceinline__ uint32_t smem_to_u32(const void* p) {
    uint32_t a;
    asm("{ .reg .u64 t; cvta.to.shared.u64 t, %1; cvt.u32.u64 %0, t; }"
        : "=r"(a) : "l"(p));
    return a;
}

#define CP_ASYNC_CG(dst, src) \
    asm volatile("cp.async.cg.shared.global [%0], [%1], 16;" :: "r"(dst), "l"(src))
#define CP_COMMIT()  asm volatile("cp.async.commit_group;" ::: "memory")
#define CP_WAIT(N)   asm volatile("cp.async.wait_group %0;" :: "n"(N) : "memory")

#define LDMATRIX_X4(r0, r1, r2, r3, addr) \
    asm volatile("ldmatrix.sync.aligned.m8n8.x4.shared.b16 {%0,%1,%2,%3}, [%4];" \
        : "=r"(r0), "=r"(r1), "=r"(r2), "=r"(r3) : "r"(addr))
#define LDMATRIX_X2(r0, r1, addr) \
    asm volatile("ldmatrix.sync.aligned.m8n8.x2.shared.b16 {%0,%1}, [%2];" \
        : "=r"(r0), "=r"(r1) : "r"(addr))
#define LDMATRIX_X4_T(r0, r1, r2, r3, addr) \
    asm volatile("ldmatrix.sync.aligned.m8n8.x4.trans.shared.b16 {%0,%1,%2,%3}, [%4];" \
        : "=r"(r0), "=r"(r1), "=r"(r2), "=r"(r3) : "r"(addr))
#define LDMATRIX_X2_T(r0, r1, addr) \
    asm volatile("ldmatrix.sync.aligned.m8n8.x2.trans.shared.b16 {%0,%1}, [%2];" \
        : "=r"(r0), "=r"(r1) : "r"(addr))

#define MMA_F16(d, a, b) \
    asm volatile("mma.sync.aligned.m16n8k16.row.col.f32.f16.f16.f32 " \
        "{%0,%1,%2,%3}, {%4,%5,%6,%7}, {%8,%9}, {%0,%1,%2,%3};" \
        : "+f"((d)[0]), "+f"((d)[1]), "+f"((d)[2]), "+f"((d)[3]) \
        : "r"((a)[0]), "r"((a)[1]), "r"((a)[2]), "r"((a)[3]), \
          "r"((b)[0]), "r"((b)[1]))

// ---------------- GEMM tiling (R10 geometry: 8 warps of 64x32) --------------
#define BM 128
#define BN 128
#define BKB 32
#define KB  (KDIM / BKB)         // 24
#define ROWB 80
#define ARR_BYTES (128 * ROWB)
#define STAGE (2 * ARR_BYTES)
#define NSTG 4
#define SMEM_GEMM (NSTG * STAGE) // 81920

__device__ __forceinline__ void gemm_mainloop(
    const __half* __restrict__ A, const __half* __restrict__ Bw,
    int bm, int bn, uint32_t sb, int tid, int wid, int lane,
    float acc[4][4][4])
{
    const int wm = (wid & 1) * 64;
    const int wn = (wid >> 1) * 32;

    const int lrow = tid >> 2;
    const int lch  = tid & 3;
    const __half* srcs[4];
    uint32_t dsts[4];
    {
        const __half* bases[2] = { A, Bw };
        #pragma unroll
        for (int i = 0; i < 4; i++) {
            int arr = i >> 1;
            int row = (i & 1) * 64 + lrow;
            int roff = (arr == 0) ? (bm + row) : (bn + row);
            srcs[i] = bases[arr] + (size_t)roff * KDIM + lch * 8;
            dsts[i] = sb + arr * ARR_BYTES + row * ROWB + lch * 16;
        }
    }

    const uint32_t a_row  = (uint32_t)(wm + (lane & 15));
    const uint32_t a_colb = (uint32_t)(((lane >> 4) & 1) * 16);
    // B x4 addressing: lane groups of 8 -> (pair-half rows, k-half columns)
    const uint32_t b_row4 = (uint32_t)(wn + ((lane >> 4) & 1) * 8 + (lane & 7));
    const uint32_t b_col4 = (uint32_t)(((lane >> 3) & 1) * 16);

    #pragma unroll
    for (int i = 0; i < 4; i++)
        #pragma unroll
        for (int j = 0; j < 4; j++)
            #pragma unroll
            for (int r = 0; r < 4; r++) acc[i][j][r] = 0.f;

    #pragma unroll
    for (int p = 0; p < 2; p++) {
        const uint32_t so = (uint32_t)(p * STAGE);
        const int k0 = p * BKB;
        #pragma unroll
        for (int i = 0; i < 4; i++) CP_ASYNC_CG(dsts[i] + so, srcs[i] + k0);
        CP_COMMIT();
    }

    for (int kb = 0; kb < KB; kb++) {
        const int pf = kb + 2;
        if (pf < KB) {
            const uint32_t so = (uint32_t)((pf & (NSTG - 1)) * STAGE);
            const int k0 = pf * BKB;
            #pragma unroll
            for (int i = 0; i < 4; i++) CP_ASYNC_CG(dsts[i] + so, srcs[i] + k0);
        }
        CP_COMMIT();
        CP_WAIT(2);
        __syncthreads();

        const uint32_t st = sb + (uint32_t)((kb & (NSTG - 1)) * STAGE);
        #pragma unroll
        for (int ks = 0; ks < 2; ks++) {
            const uint32_t kB = (uint32_t)(ks * 32);
            uint32_t af[4][4], bf[4][2];
            #pragma unroll
            for (int mt = 0; mt < 4; mt++) {
                uint32_t ao = st + (a_row + mt * 16) * ROWB + kB + a_colb;
                LDMATRIX_X4(af[mt][0], af[mt][1], af[mt][2], af[mt][3], ao);
            }
            // B: two x4 loads cover nt = {0,1} and {2,3}
            #pragma unroll
            for (int pr = 0; pr < 2; pr++) {
                uint32_t bo = st + ARR_BYTES + (b_row4 + pr * 16) * ROWB + kB + b_col4;
                LDMATRIX_X4(bf[2 * pr][0], bf[2 * pr][1],
                            bf[2 * pr + 1][0], bf[2 * pr + 1][1], bo);
            }
            #pragma unroll
            for (int mt = 0; mt < 4; mt++)
                #pragma unroll
                for (int nt = 0; nt < 4; nt++)
                    MMA_F16(acc[mt][nt], af[mt], bf[nt]);
        }
    }
}

// ---------------- GEMM1: qkv with fused bias+rope+softmax+scatter ----------
#define EPS 132

__global__ __launch_bounds__(256, 2)
void mma_gemm_qkv(const __half* __restrict__ A, const __half* __restrict__ Bw,
                  const float* __restrict__ rope,
                  const float* __restrict__ q_bias, const float* __restrict__ v_bias,
                  __half* __restrict__ phiq, __half* __restrict__ phik, __half* __restrict__ vout)
{
    extern __shared__ char smem[];
    const uint32_t sb = smem_to_u32(smem);
    const int tid = threadIdx.x, wid = tid >> 5, lane = tid & 31;
    const int bm = blockIdx.y * BM, bn = blockIdx.x * BN;

    float acc[4][4][4];
    gemm_mainloop(A, Bw, bm, bn, sb, tid, wid, lane, acc);
    __syncthreads();

    float* epi = (float*)smem;
    const int wm = (wid & 1) * 64, wn = (wid >> 1) * 32;
    const int er = lane >> 2, ec = (lane & 3) * 2;
    #pragma unroll
    for (int mt = 0; mt < 4; mt++)
        #pragma unroll
        for (int nt = 0; nt < 4; nt++) {
            int r0 = wm + mt * 16 + er, c = wn + nt * 8 + ec;
            *(float2*)&epi[r0 * EPS + c]       = make_float2(acc[mt][nt][0], acc[mt][nt][1]);
            *(float2*)&epi[(r0 + 8) * EPS + c] = make_float2(acc[mt][nt][2], acc[mt][nt][3]);
        }
    __syncthreads();

    const int region = bn / C_;
    const int col0   = bn - region * C_;
    const float* bias = (region == 0) ? q_bias : (region == 2 ? v_bias : nullptr);
    __half* outbuf = (region == 0) ? phiq : (region == 1 ? phik : vout);

    const int sub    = lane >> 4;
    const int lane15 = lane & 15;
    const int g      = lane15 >> 3;
    const int dof    = (lane15 & 7) << 3;
    const int h      = (col0 >> 6) + g;

    #pragma unroll 2
    for (int rr = 0; rr < 8; rr++) {
        const int row  = wid * 16 + rr * 2 + sub;
        const int gtok = bm + row;
        const int b    = gtok >> 12;
        const int n    = gtok & (NTOK - 1);

        float4 v0 = *(float4*)&epi[row * EPS + g * 64 + dof];
        float4 v1 = *(float4*)&epi[row * EPS + g * 64 + dof + 4];
        float vals[8] = { v0.x, v0.y, v0.z, v0.w, v1.x, v1.y, v1.z, v1.w };

        if (bias) {
            #pragma unroll
            for (int j = 0; j < 8; j++) vals[j] += bias[col0 + g * 64 + dof + j];
        }

        if (region != 2) {
            if (n >= 1) {
                const float* rp = rope + (size_t)(n - 1) * (2 * D_) + dof;
                float4 s0 = *(const float4*)rp;
                float4 s1 = *(const float4*)(rp + 4);
                float4 c0 = *(const float4*)(rp + 64);
                float4 c1 = *(const float4*)(rp + 68);
                float snv[8] = { s0.x, s0.y, s0.z, s0.w, s1.x, s1.y, s1.z, s1.w };
                float csv[8] = { c0.x, c0.y, c0.z, c0.w, c1.x, c1.y, c1.z, c1.w };
                #pragma unroll
                for (int p = 0; p < 4; p++) {
                    float t0 = vals[2 * p], t1 = vals[2 * p + 1];
                    vals[2 * p]     = t0 * csv[2 * p]     - t1 * snv[2 * p];
                    vals[2 * p + 1] = t1 * csv[2 * p + 1] + t0 * snv[2 * p + 1];
                }
            }
            float m = vals[0];
            #pragma unroll
            for (int j = 1; j < 8; j++) m = fmaxf(m, vals[j]);
            #pragma unroll
            for (int o = 1; o < 8; o <<= 1)
                m = fmaxf(m, __shfl_xor_sync(0xffffffffu, m, o));
            float s = 0.f;
            #pragma unroll
            for (int j = 0; j < 8; j++) { vals[j] = expf(vals[j] - m); s += vals[j]; }
            #pragma unroll
            for (int o = 1; o < 8; o <<= 1)
                s += __shfl_xor_sync(0xffffffffu, s, o);
            float rs = 1.f / s;
            #pragma unroll
            for (int j = 0; j < 8; j++) vals[j] *= rs;
        }

        __half hv[8];
        #pragma unroll
        for (int j = 0; j < 8; j++) hv[j] = __float2half(vals[j]);
        __half* dst = outbuf + (((size_t)b * H_ + h) * NTOK + n) * D_ + dof;
        *(uint4*)dst = *(uint4*)hv;
    }
}

// ---------------- GEMM2: proj with bias ----------------
__global__ __launch_bounds__(256, 2)
void mma_gemm_proj(const __half* __restrict__ A, const __half* __restrict__ Bw,
                   float* __restrict__ Cc, int N, const float* __restrict__ bias_full)
{
    extern __shared__ char smem[];
    const uint32_t sb = smem_to_u32(smem);
    const int tid = threadIdx.x, wid = tid >> 5, lane = tid & 31;
    const int bm = blockIdx.y * BM, bn = blockIdx.x * BN;

    float acc[4][4][4];
    gemm_mainloop(A, Bw, bm, bn, sb, tid, wid, lane, acc);

    const int wm = (wid & 1) * 64, wn = (wid >> 1) * 32;
    const int er = lane >> 2, ec = (lane & 3) * 2;
    #pragma unroll
    for (int mt = 0; mt < 4; mt++) {
        #pragma unroll
        for (int nt = 0; nt < 4; nt++) {
            int row = bm + wm + mt * 16 + er;
            int col = bn + wn + nt * 8 + ec;
            float b0 = bias_full[col], b1 = bias_full[col + 1];
            *(float2*)(Cc + (size_t)row * N + col) =
                make_float2(acc[mt][nt][0] + b0, acc[mt][nt][1] + b1);
            *(float2*)(Cc + (size_t)(row + 8) * N + col) =
                make_float2(acc[mt][nt][2] + b0, acc[mt][nt][3] + b1);
        }
    }
}

// ---------------- kv via mma, 4-way split over tokens ----------------
#define KROWB 144
#define KARR  (64 * KROWB)
#define KSTG  (2 * KARR)
#define SEGTOK (NTOK / KVSEG)          // 1024 tokens per segment

__global__ __launch_bounds__(128)
void kv_mma_kernel(const __half* __restrict__ phik, const __half* __restrict__ v,
                   float* __restrict__ kvp, float* __restrict__ ksp)
{
    __shared__ char skv[2 * KSTG];
    __shared__ float sred[2][64];
    const uint32_t sb = smem_to_u32(skv);
    const int tid = threadIdx.x, wid = tid >> 5, lane = tid & 31;
    const int bh = blockIdx.x;
    const int seg = blockIdx.y;
    const int nbase = seg * SEGTOK;

    const __half* pk = phik + (size_t)bh * NTOK * D_;
    const __half* pv = v    + (size_t)bh * NTOK * D_;

    const int wd = wid & 1, we = wid >> 1;

    const int akk = (lane & 7) + ((lane >> 4) & 1) * 8;
    const int amm = ((lane >> 3) & 1) * 8;
    const int bkk = (lane & 7) + ((lane >> 3) & 1) * 8;

    float acc[2][4][4];
    #pragma unroll
    for (int i = 0; i < 2; i++)
        #pragma unroll
        for (int j = 0; j < 4; j++)
            #pragma unroll
            for (int r = 0; r < 4; r++) acc[i][j][r] = 0.f;

    float ksl = 0.f;
    const int dloc = tid & 63, rg = tid >> 6;

    auto fill = [&](int kb, int slot) {
        const int n0 = nbase + kb * 64;
        const uint32_t so = sb + (uint32_t)(slot * KSTG);
        #pragma unroll
        for (int i = tid; i < 1024; i += 128) {
            int arr = i >> 9;
            int r   = (i >> 3) & 63;
            int ch  = i & 7;
            const __half* src = (arr ? pv : pk) + (size_t)(n0 + r) * D_ + ch * 8;
            CP_ASYNC_CG(so + arr * KARR + r * KROWB + ch * 16, src);
        }
    };

    fill(0, 0); CP_COMMIT();

    const int NBLK = SEGTOK / 64;   // 16
    for (int kb = 0; kb < NBLK; kb++) {
        __syncthreads();
        if (kb + 1 < NBLK) { fill(kb + 1, (kb + 1) & 1); CP_COMMIT(); CP_WAIT(1); }
        else               { CP_WAIT(0); }
        __syncthreads();

        const uint32_t st = sb + (uint32_t)((kb & 1) * KSTG);

        const __half* ph = (const __half*)(skv + (kb & 1) * KSTG);
        #pragma unroll 8
        for (int r = rg * 32; r < rg * 32 + 32; r++)
            ksl += __half2float(*(const __half*)((const char*)ph + r * KROWB + dloc * 2));

        #pragma unroll
        for (int ks = 0; ks < 4; ks++) {
            const int k0 = ks * 16;
            uint32_t af[2][4], bf[4][2];
            #pragma unroll
            for (int mt = 0; mt < 2; mt++) {
                uint32_t ao = st + (k0 + akk) * KROWB + (wd * 32 + mt * 16 + amm) * 2;
                LDMATRIX_X4_T(af[mt][0], af[mt][1], af[mt][2], af[mt][3], ao);
            }
            #pragma unroll
            for (int nt = 0; nt < 4; nt++) {
                uint32_t bo = st + KARR + (k0 + bkk) * KROWB + (we * 32 + nt * 8) * 2;
                LDMATRIX_X2_T(bf[nt][0], bf[nt][1], bo);
            }
            #pragma unroll
            for (int mt = 0; mt < 2; mt++)
                #pragma unroll
                for (int nt = 0; nt < 4; nt++)
                    MMA_F16(acc[mt][nt], af[mt], bf[nt]);
        }
    }

    // write fp32 partials [seg][bh][e][d]
    const int er = lane >> 2, ec = (lane & 3) * 2;
    float* kvb = kvp + ((size_t)seg * B_ * H_ + bh) * D_ * D_;
    #pragma unroll
    for (int mt = 0; mt < 2; mt++)
        #pragma unroll
        for (int nt = 0; nt < 4; nt++) {
            int d = wd * 32 + mt * 16 + er;
            int e = we * 32 + nt * 8 + ec;
            kvb[(e)     * D_ + d]     = acc[mt][nt][0];
            kvb[(e + 1) * D_ + d]     = acc[mt][nt][1];
            kvb[(e)     * D_ + d + 8] = acc[mt][nt][2];
            kvb[(e + 1) * D_ + d + 8] = acc[mt][nt][3];
        }

    sred[rg][dloc] = ksl;
    __syncthreads();
    if (rg == 0) ksp[(seg * B_ * H_ + bh) * D_ + dloc] = sred[0][dloc] + sred[1][dloc];
}

// ---------------- kv partial reduce -> kvT fp16 + ksum -----------------------
__global__ __launch_bounds__(256)
void kv_reduce_kernel(const float* __restrict__ kvp, const float* __restrict__ ksp,
                      __half* __restrict__ kvT, float* __restrict__ ksum)
{
    const int bh = blockIdx.x, tid = threadIdx.x;
    #pragma unroll 4
    for (int i = tid; i < D_ * D_; i += 256) {
        float s = 0.f;
        #pragma unroll
        for (int sg = 0; sg < KVSEG; sg++)
            s += kvp[((size_t)sg * B_ * H_ + bh) * D_ * D_ + i];
        kvT[(size_t)bh * D_ * D_ + i] = __float2half(s);
    }
    if (tid < D_) {
        float s = 0.f;
        #pragma unroll
        for (int sg = 0; sg < KVSEG; sg++)
            s += ksp[(sg * B_ * H_ + bh) * D_ + tid];
        ksum[bh * D_ + tid] = s;
    }
}

// ---------------- attn via mma (unchanged from R10) ----------------
__global__ __launch_bounds__(256)
void attn_mma_kernel(const __half* __restrict__ phiq, const __half* __restrict__ kvT,
                     const float* __restrict__ ksum, __half* __restrict__ attn)
{
    __shared__ __half phq[128 * 72];
    __shared__ __half kvt[64 * 72];
    __shared__ float ksm[64];
    __shared__ float zpart[128][2];
    __shared__ float zb[128];

    const int tid = threadIdx.x, wid = tid >> 5, lane = tid & 31;
    const int bh = blockIdx.x;
    const int n0 = blockIdx.y * 128;
    const int b = bh / H_, h = bh % H_;

    const __half* pq = phiq + ((size_t)bh * NTOK + n0) * D_;
    const __half* kb = kvT + (size_t)bh * D_ * D_;

    #pragma unroll
    for (int i = tid; i < 1024; i += 256) {
        int r = i >> 3, ch = i & 7;
        *(uint4*)&phq[r * 72 + ch * 8] = *(const uint4*)(pq + (size_t)r * D_ + ch * 8);
    }
    #pragma unroll
    for (int i = tid; i < 512; i += 256) {
        int r = i >> 3, ch = i & 7;
        *(uint4*)&kvt[r * 72 + ch * 8] = *(const uint4*)(kb + (size_t)r * D_ + ch * 8);
    }
    if (tid < 64) ksm[tid] = ksum[bh * D_ + tid];
    __syncthreads();

    {
        int row = tid >> 1, hh = tid & 1;
        float z = 0.f;
        #pragma unroll 8
        for (int d = hh * 32; d < hh * 32 + 32; d++)
            z += __half2float(phq[row * 72 + d]) * ksm[d];
        zpart[row][hh] = z;
    }
    __syncthreads();
    if (tid < 128) zb[tid] = 1.f / (zpart[tid][0] + zpart[tid][1] + 1e-5f);

    const int wm2 = (wid & 3) * 32, wn2 = (wid >> 2) * 32;
    const uint32_t pq32 = smem_to_u32(phq), kv32 = smem_to_u32(kvt);
    float acc[2][4][4];
    #pragma unroll
    for (int i = 0; i < 2; i++)
        #pragma unroll
        for (int j = 0; j < 4; j++)
            #pragma unroll
            for (int r = 0; r < 4; r++) acc[i][j][r] = 0.f;

    #pragma unroll
    for (int ks = 0; ks < 4; ks++) {
        const int k0 = ks * 16;
        uint32_t af[2][4], bf[4][2];
        #pragma unroll
        for (int mt = 0; mt < 2; mt++) {
            uint32_t ao = pq32 + (wm2 + mt * 16 + (lane & 15)) * 144 + (k0 + ((lane >> 4) & 1) * 8) * 2;
            LDMATRIX_X4(af[mt][0], af[mt][1], af[mt][2], af[mt][3], ao);
        }
        #pragma unroll
        for (int nt = 0; nt < 4; nt++) {
            uint32_t bo = kv32 + (wn2 + nt * 8 + (lane & 7)) * 144 + (k0 + ((lane >> 3) & 1) * 8) * 2;
            LDMATRIX_X2(bf[nt][0], bf[nt][1], bo);
        }
        #pragma unroll
        for (int mt = 0; mt < 2; mt++)
            #pragma unroll
            for (int nt = 0; nt < 4; nt++)
                MMA_F16(acc[mt][nt], af[mt], bf[nt]);
    }
    __syncthreads();

    const int er = lane >> 2, ec = (lane & 3) * 2;
    #pragma unroll
    for (int mt = 0; mt < 2; mt++)
        #pragma unroll
        for (int nt = 0; nt < 4; nt++) {
            int row = wm2 + mt * 16 + er;
            int e   = wn2 + nt * 8 + ec;
            float rz0 = zb[row], rz1 = zb[row + 8];
            size_t base0 = ((size_t)(b * NTOK + n0 + row)) * C_ + h * D_ + e;
            size_t base1 = ((size_t)(b * NTOK + n0 + row + 8)) * C_ + h * D_ + e;
            __half2 o0 = __floats2half2_rn(acc[mt][nt][0] * rz0, acc[mt][nt][1] * rz0);
            __half2 o1 = __floats2half2_rn(acc[mt][nt][2] * rz1, acc[mt][nt][3] * rz1);
            *(__half2*)(attn + base0) = o0;
            *(__half2*)(attn + base1) = o1;
        }
}

// ---------------- fp32 -> fp16 ----------------
__global__ void cvt_h(const float* __restrict__ x, __half* __restrict__ y, int n4)
{
    int i = blockIdx.x * blockDim.x + threadIdx.x;
    if (i >= n4) return;
    float4 f = ((const float4*)x)[i];
    __half h[4];
    h[0] = __float2half(f.x); h[1] = __float2half(f.y);
    h[2] = __float2half(f.z); h[3] = __float2half(f.w);
    ((uint2*)y)[i] = *(uint2*)h;
}

// ---------------- layernorm (fp16 in) -> fp16 --------------------------------
__global__ void ln_kernel(const __half* __restrict__ x,
                          const float* __restrict__ g,
                          const float* __restrict__ b,
                          __half* __restrict__ yh)
{
    int row = blockIdx.x;
    int tid = threadIdx.x; // 256
    const __half* xr = x + (size_t)row * C_;

    float v0 = __half2float(xr[tid]);
    float v1 = __half2float(xr[tid + 256]);
    float v2 = __half2float(xr[tid + 512]);
    float s  = v0 + v1 + v2;
    float ss = v0 * v0 + v1 * v1 + v2 * v2;
#pragma unroll
    for (int o = 16; o > 0; o >>= 1) {
        s  += __shfl_xor_sync(0xffffffffu, s,  o);
        ss += __shfl_xor_sync(0xffffffffu, ss, o);
    }
    __shared__ float ws[8], wss[8];
    int warp = tid >> 5, lane = tid & 31;
    if (lane == 0) { ws[warp] = s; wss[warp] = ss; }
    __syncthreads();
    if (tid == 0) {
        float ts = 0.f, tss = 0.f;
#pragma unroll
        for (int i = 0; i < 8; i++) { ts += ws[i]; tss += wss[i]; }
        ws[0] = ts; wss[0] = tss;
    }
    __syncthreads();
    float mean = ws[0] * (1.f / C_);
    float var  = wss[0] * (1.f / C_) - mean * mean;
    float inv  = rsqrtf(var + 1e-5f);

    size_t rb = (size_t)row * C_;
#pragma unroll
    for (int j = 0; j < 3; j++) {
        int c = tid + j * 256;
        float vv = (j == 0 ? v0 : (j == 1 ? v1 : v2));
        float y = (vv - mean) * inv * g[c] + b[c];
        yh[rb + c] = __float2half(y);
    }
}

// ---------------- launch ------------------------------------------------------
extern "C" void kernel_launch(void* const* d_in, const int* in_sizes, int n_in,
                              void* d_out, int out_size)
{
    (void)in_sizes; (void)n_in; (void)out_size;
    const float* x      = (const float*)d_in[0];
    const float* rope   = (const float*)d_in[1];
    const float* qkv_w  = (const float*)d_in[2];
    const float* q_bias = (const float*)d_in[3];
    const float* v_bias = (const float*)d_in[4];
    const float* norm_g = (const float*)d_in[5];
    const float* norm_b = (const float*)d_in[6];
    const float* proj_w = (const float*)d_in[7];
    const float* proj_b = (const float*)d_in[8];
    float* out = (float*)d_out;

    float *ksum, *kvp, *ksp;
    __half *phiq, *phik, *v, *kvT, *attn, *xh, *w, *pw, *lh;
    cudaGetSymbolAddress((void**)&phiq, g_phiq);
    cudaGetSymbolAddress((void**)&phik, g_phik);
    cudaGetSymbolAddress((void**)&v,    g_v);
    cudaGetSymbolAddress((void**)&kvT,  g_kvT);
    cudaGetSymbolAddress((void**)&kvp,  g_kvp);
    cudaGetSymbolAddress((void**)&ksum, g_ksum);
    cudaGetSymbolAddress((void**)&ksp,  g_ksp);
    cudaGetSymbolAddress((void**)&attn, g_attn);
    cudaGetSymbolAddress((void**)&xh,   g_xh);
    cudaGetSymbolAddress((void**)&w,    g_w);
    cudaGetSymbolAddress((void**)&pw,   g_pw);
    cudaGetSymbolAddress((void**)&lh,   g_lh);

    cudaFuncSetAttribute(mma_gemm_qkv,  cudaFuncAttributeMaxDynamicSharedMemorySize, SMEM_GEMM);
    cudaFuncSetAttribute(mma_gemm_proj, cudaFuncAttributeMaxDynamicSharedMemorySize, SMEM_GEMM);

    // 0) conversions
    {
        int n4 = (M_ * KDIM) / 4;
        cvt_h<<<(n4 + 255) / 256, 256>>>(x, xh, n4);
        n4 = (QKVN * KDIM) / 4;
        cvt_h<<<(n4 + 255) / 256, 256>>>(qkv_w, w, n4);
        n4 = (C_ * KDIM) / 4;
        cvt_h<<<(n4 + 255) / 256, 256>>>(proj_w, pw, n4);
    }

    // 1) fused qkv GEMM + bias + rope + softmax + head-scatter (fp16 out)
    mma_gemm_qkv<<<dim3(QKVN / BN, M_ / BM), 256, SMEM_GEMM>>>(
        xh, w, rope, q_bias, v_bias, phiq, phik, v);

    // 2) kv partials via tensor cores (4-way token split), then reduce
    kv_mma_kernel<<<dim3(B_ * H_, KVSEG), 128>>>(phik, v, kvp, ksp);
    kv_reduce_kernel<<<B_ * H_, 256>>>(kvp, ksp, kvT, ksum);

    // 3) attention output via tensor cores
    attn_mma_kernel<<<dim3(B_ * H_, NTOK / 128), 256>>>(phiq, kvT, ksum, attn);

    // 4) layernorm (fp16 -> fp16)
    ln_kernel<<<M_, 256>>>(attn, norm_g, norm_b, lh);

    // 5) out = ln @ proj_w^T + proj_b
    mma_gemm_proj<<<dim3(C_ / BN, M_ / BM), 256, SMEM_GEMM>>>(
        lh, pw, out, C_, proj_b);
}

// round 13
// speedup vs baseline: 1.4995x; 1.0049x over previous
#include <cuda_runtime.h>
#include <cuda_fp16.h>
#include <cstdint>

// ---------------- problem constants ----------------
#define B_    8
#define NTOK  4096
#define C_    768
#define H_    12
#define D_    64
#define M_    (B_ * NTOK)     // 32768
#define QKVN  (3 * C_)        // 2304
#define KDIM  768
#define KVSEG 4               // kv split segments

// ---------------- scratch (device globals) ----------------
__device__ __half g_phiq[(size_t)B_ * H_ * NTOK * D_];
__device__ __half g_phik[(size_t)B_ * H_ * NTOK * D_];
__device__ __half g_v   [(size_t)B_ * H_ * NTOK * D_];
__device__ __half g_kvT [B_ * H_ * D_ * D_];          // [bh][e][d]
__device__ float  g_kvp [KVSEG * B_ * H_ * D_ * D_];  // fp32 partials
__device__ float  g_ksum[B_ * H_ * D_];
__device__ float  g_ksp [KVSEG * B_ * H_ * D_];
__device__ __half g_attn[(size_t)M_ * C_];

__device__ __half g_xh [(size_t)M_ * KDIM];
__device__ __half g_w  [(size_t)QKVN * KDIM];
__device__ __half g_pw [(size_t)C_ * KDIM];
__device__ __half g_lh [(size_t)M_ * KDIM];

// ---------------- low-level helpers ----------------
__device__ __forceinline__ uint32_t smem_to_u32(const void* p) {
    uint32_t a;
    asm("{ .reg .u64 t; cvta.to.shared.u64 t, %1; cvt.u32.u64 %0, t; }"
        : "=r"(a) : "l"(p));
    return a;
}

#define CP_ASYNC_CG(dst, src) \
    asm volatile("cp.async.cg.shared.global [%0], [%1], 16;" :: "r"(dst), "l"(src))
#define CP_COMMIT()  asm volatile("cp.async.commit_group;" ::: "memory")
#define CP_WAIT(N)   asm volatile("cp.async.wait_group %0;" :: "n"(N) : "memory")

#define LDMATRIX_X4(r0, r1, r2, r3, addr) \
    asm volatile("ldmatrix.sync.aligned.m8n8.x4.shared.b16 {%0,%1,%2,%3}, [%4];" \
        : "=r"(r0), "=r"(r1), "=r"(r2), "=r"(r3) : "r"(addr))
#define LDMATRIX_X2(r0, r1, addr) \
    asm volatile("ldmatrix.sync.aligned.m8n8.x2.shared.b16 {%0,%1}, [%2];" \
        : "=r"(r0), "=r"(r1) : "r"(addr))
#define LDMATRIX_X4_T(r0, r1, r2, r3, addr) \
    asm volatile("ldmatrix.sync.aligned.m8n8.x4.trans.shared.b16 {%0,%1,%2,%3}, [%4];" \
        : "=r"(r0), "=r"(r1), "=r"(r2), "=r"(r3) : "r"(addr))
#define LDMATRIX_X2_T(r0, r1, addr) \
    asm volatile("ldmatrix.sync.aligned.m8n8.x2.trans.shared.b16 {%0,%1}, [%2];" \
        : "=r"(r0), "=r"(r1) : "r"(addr))

#define MMA_F16(d, a, b) \
    asm volatile("mma.sync.aligned.m16n8k16.row.col.f32.f16.f16.f32 " \
        "{%0,%1,%2,%3}, {%4,%5,%6,%7}, {%8,%9}, {%0,%1,%2,%3};" \
        : "+f"((d)[0]), "+f"((d)[1]), "+f"((d)[2]), "+f"((d)[3]) \
        : "r"((a)[0]), "r"((a)[1]), "r"((a)[2]), "r"((a)[3]), \
          "r"((b)[0]), "r"((b)[1]))

// ---------------- GEMM tiling (R12 geometry: 8 warps of 64x32) --------------
#define BM 128
#define BN 128
#define BKB 32
#define KB  (KDIM / BKB)         // 24
#define ROWB 80
#define ARR_BYTES (128 * ROWB)
#define STAGE (2 * ARR_BYTES)
#define NSTG 4
#define SMEM_GEMM (NSTG * STAGE) // 81920

__device__ __forceinline__ void gemm_mainloop(
    const __half* __restrict__ A, const __half* __restrict__ Bw,
    int bm, int bn, uint32_t sb, int tid, int wid, int lane,
    float acc[4][4][4])
{
    const int wm = (wid & 1) * 64;
    const int wn = (wid >> 1) * 32;

    const int lrow = tid >> 2;
    const int lch  = tid & 3;
    const __half* srcs[4];
    uint32_t dsts[4];
    {
        const __half* bases[2] = { A, Bw };
        #pragma unroll
        for (int i = 0; i < 4; i++) {
            int arr = i >> 1;
            int row = (i & 1) * 64 + lrow;
            int roff = (arr == 0) ? (bm + row) : (bn + row);
            srcs[i] = bases[arr] + (size_t)roff * KDIM + lch * 8;
            dsts[i] = sb + arr * ARR_BYTES + row * ROWB + lch * 16;
        }
    }

    const uint32_t a_row  = (uint32_t)(wm + (lane & 15));
    const uint32_t a_colb = (uint32_t)(((lane >> 4) & 1) * 16);
    const uint32_t b_row4 = (uint32_t)(wn + ((lane >> 4) & 1) * 8 + (lane & 7));
    const uint32_t b_col4 = (uint32_t)(((lane >> 3) & 1) * 16);

    #pragma unroll
    for (int i = 0; i < 4; i++)
        #pragma unroll
        for (int j = 0; j < 4; j++)
            #pragma unroll
            for (int r = 0; r < 4; r++) acc[i][j][r] = 0.f;

    #pragma unroll
    for (int p = 0; p < 2; p++) {
        const uint32_t so = (uint32_t)(p * STAGE);
        const int k0 = p * BKB;
        #pragma unroll
        for (int i = 0; i < 4; i++) CP_ASYNC_CG(dsts[i] + so, srcs[i] + k0);
        CP_COMMIT();
    }

    for (int kb = 0; kb < KB; kb++) {
        const int pf = kb + 2;
        if (pf < KB) {
            const uint32_t so = (uint32_t)((pf & (NSTG - 1)) * STAGE);
            const int k0 = pf * BKB;
            #pragma unroll
            for (int i = 0; i < 4; i++) CP_ASYNC_CG(dsts[i] + so, srcs[i] + k0);
        }
        CP_COMMIT();
        CP_WAIT(2);
        __syncthreads();

        const uint32_t st = sb + (uint32_t)((kb & (NSTG - 1)) * STAGE);
        #pragma unroll
        for (int ks = 0; ks < 2; ks++) {
            const uint32_t kB = (uint32_t)(ks * 32);
            uint32_t bf[4][2];
            // B first: two x4 loads cover nt = {0,1} and {2,3}
            #pragma unroll
            for (int pr = 0; pr < 2; pr++) {
                uint32_t bo = st + ARR_BYTES + (b_row4 + pr * 16) * ROWB + kB + b_col4;
                LDMATRIX_X4(bf[2 * pr][0], bf[2 * pr][1],
                            bf[2 * pr + 1][0], bf[2 * pr + 1][1], bo);
            }
            // per m-row: load A fragment then immediately issue its MMAs —
            // shortens the ldsm->mma dependency chain and gives 4 independent
            // streams for the scheduler to overlap.
            #pragma unroll
            for (int mt = 0; mt < 4; mt++) {
                uint32_t af[4];
                uint32_t ao = st + (a_row + mt * 16) * ROWB + kB + a_colb;
                LDMATRIX_X4(af[0], af[1], af[2], af[3], ao);
                #pragma unroll
                for (int nt = 0; nt < 4; nt++)
                    MMA_F16(acc[mt][nt], af, bf[nt]);
            }
        }
    }
}

// ---------------- GEMM1: qkv with fused bias+rope+softmax+scatter ----------
#define EPS 132

__global__ __launch_bounds__(256, 2)
void mma_gemm_qkv(const __half* __restrict__ A, const __half* __restrict__ Bw,
                  const float* __restrict__ rope,
                  const float* __restrict__ q_bias, const float* __restrict__ v_bias,
                  __half* __restrict__ phiq, __half* __restrict__ phik, __half* __restrict__ vout)
{
    extern __shared__ char smem[];
    const uint32_t sb = smem_to_u32(smem);
    const int tid = threadIdx.x, wid = tid >> 5, lane = tid & 31;
    const int bm = blockIdx.y * BM, bn = blockIdx.x * BN;

    float acc[4][4][4];
    gemm_mainloop(A, Bw, bm, bn, sb, tid, wid, lane, acc);
    __syncthreads();

    float* epi = (float*)smem;
    const int wm = (wid & 1) * 64, wn = (wid >> 1) * 32;
    const int er = lane >> 2, ec = (lane & 3) * 2;
    #pragma unroll
    for (int mt = 0; mt < 4; mt++)
        #pragma unroll
        for (int nt = 0; nt < 4; nt++) {
            int r0 = wm + mt * 16 + er, c = wn + nt * 8 + ec;
            *(float2*)&epi[r0 * EPS + c]       = make_float2(acc[mt][nt][0], acc[mt][nt][1]);
            *(float2*)&epi[(r0 + 8) * EPS + c] = make_float2(acc[mt][nt][2], acc[mt][nt][3]);
        }
    __syncthreads();

    const int region = bn / C_;
    const int col0   = bn - region * C_;
    const float* bias = (region == 0) ? q_bias : (region == 2 ? v_bias : nullptr);
    __half* outbuf = (region == 0) ? phiq : (region == 1 ? phik : vout);

    const int sub    = lane >> 4;
    const int lane15 = lane & 15;
    const int g      = lane15 >> 3;
    const int dof    = (lane15 & 7) << 3;
    const int h      = (col0 >> 6) + g;

    #pragma unroll 2
    for (int rr = 0; rr < 8; rr++) {
        const int row  = wid * 16 + rr * 2 + sub;
        const int gtok = bm + row;
        const int b    = gtok >> 12;
        const int n    = gtok & (NTOK - 1);

        float4 v0 = *(float4*)&epi[row * EPS + g * 64 + dof];
        float4 v1 = *(float4*)&epi[row * EPS + g * 64 + dof + 4];
        float vals[8] = { v0.x, v0.y, v0.z, v0.w, v1.x, v1.y, v1.z, v1.w };

        if (bias) {
            #pragma unroll
            for (int j = 0; j < 8; j++) vals[j] += bias[col0 + g * 64 + dof + j];
        }

        if (region != 2) {
            if (n >= 1) {
                const float* rp = rope + (size_t)(n - 1) * (2 * D_) + dof;
                float4 s0 = *(const float4*)rp;
                float4 s1 = *(const float4*)(rp + 4);
                float4 c0 = *(const float4*)(rp + 64);
                float4 c1 = *(const float4*)(rp + 68);
                float snv[8] = { s0.x, s0.y, s0.z, s0.w, s1.x, s1.y, s1.z, s1.w };
                float csv[8] = { c0.x, c0.y, c0.z, c0.w, c1.x, c1.y, c1.z, c1.w };
                #pragma unroll
                for (int p = 0; p < 4; p++) {
                    float t0 = vals[2 * p], t1 = vals[2 * p + 1];
                    vals[2 * p]     = t0 * csv[2 * p]     - t1 * snv[2 * p];
                    vals[2 * p + 1] = t1 * csv[2 * p + 1] + t0 * snv[2 * p + 1];
                }
            }
            float m = vals[0];
            #pragma unroll
            for (int j = 1; j < 8; j++) m = fmaxf(m, vals[j]);
            #pragma unroll
            for (int o = 1; o < 8; o <<= 1)
                m = fmaxf(m, __shfl_xor_sync(0xffffffffu, m, o));
            float s = 0.f;
            #pragma unroll
            for (int j = 0; j < 8; j++) { vals[j] = expf(vals[j] - m); s += vals[j]; }
            #pragma unroll
            for (int o = 1; o < 8; o <<= 1)
                s += __shfl_xor_sync(0xffffffffu, s, o);
            float rs = 1.f / s;
            #pragma unroll
            for (int j = 0; j < 8; j++) vals[j] *= rs;
        }

        __half hv[8];
        #pragma unroll
        for (int j = 0; j < 8; j++) hv[j] = __float2half(vals[j]);
        __half* dst = outbuf + (((size_t)b * H_ + h) * NTOK + n) * D_ + dof;
        *(uint4*)dst = *(uint4*)hv;
    }
}

// ---------------- GEMM2: proj with bias ----------------
__global__ __launch_bounds__(256, 2)
void mma_gemm_proj(const __half* __restrict__ A, const __half* __restrict__ Bw,
                   float* __restrict__ Cc, int N, const float* __restrict__ bias_full)
{
    extern __shared__ char smem[];
    const uint32_t sb = smem_to_u32(smem);
    const int tid = threadIdx.x, wid = tid >> 5, lane = tid & 31;
    const int bm = blockIdx.y * BM, bn = blockIdx.x * BN;

    float acc[4][4][4];
    gemm_mainloop(A, Bw, bm, bn, sb, tid, wid, lane, acc);

    const int wm = (wid & 1) * 64, wn = (wid >> 1) * 32;
    const int er = lane >> 2, ec = (lane & 3) * 2;
    #pragma unroll
    for (int mt = 0; mt < 4; mt++) {
        #pragma unroll
        for (int nt = 0; nt < 4; nt++) {
            int row = bm + wm + mt * 16 + er;
            int col = bn + wn + nt * 8 + ec;
            float b0 = bias_full[col], b1 = bias_full[col + 1];
            *(float2*)(Cc + (size_t)row * N + col) =
                make_float2(acc[mt][nt][0] + b0, acc[mt][nt][1] + b1);
            *(float2*)(Cc + (size_t)(row + 8) * N + col) =
                make_float2(acc[mt][nt][2] + b0, acc[mt][nt][3] + b1);
        }
    }
}

// ---------------- kv via mma, 4-way split over tokens ----------------
#define KROWB 144
#define KARR  (64 * KROWB)
#define KSTG  (2 * KARR)
#define SEGTOK (NTOK / KVSEG)

__global__ __launch_bounds__(128)
void kv_mma_kernel(const __half* __restrict__ phik, const __half* __restrict__ v,
                   float* __restrict__ kvp, float* __restrict__ ksp)
{
    __shared__ char skv[2 * KSTG];
    __shared__ float sred[2][64];
    const uint32_t sb = smem_to_u32(skv);
    const int tid = threadIdx.x, wid = tid >> 5, lane = tid & 31;
    const int bh = blockIdx.x;
    const int seg = blockIdx.y;
    const int nbase = seg * SEGTOK;

    const __half* pk = phik + (size_t)bh * NTOK * D_;
    const __half* pv = v    + (size_t)bh * NTOK * D_;

    const int wd = wid & 1, we = wid >> 1;

    const int akk = (lane & 7) + ((lane >> 4) & 1) * 8;
    const int amm = ((lane >> 3) & 1) * 8;
    const int bkk = (lane & 7) + ((lane >> 3) & 1) * 8;

    float acc[2][4][4];
    #pragma unroll
    for (int i = 0; i < 2; i++)
        #pragma unroll
        for (int j = 0; j < 4; j++)
            #pragma unroll
            for (int r = 0; r < 4; r++) acc[i][j][r] = 0.f;

    float ksl = 0.f;
    const int dloc = tid & 63, rg = tid >> 6;

    auto fill = [&](int kb, int slot) {
        const int n0 = nbase + kb * 64;
        const uint32_t so = sb + (uint32_t)(slot * KSTG);
        #pragma unroll
        for (int i = tid; i < 1024; i += 128) {
            int arr = i >> 9;
            int r   = (i >> 3) & 63;
            int ch  = i & 7;
            const __half* src = (arr ? pv : pk) + (size_t)(n0 + r) * D_ + ch * 8;
            CP_ASYNC_CG(so + arr * KARR + r * KROWB + ch * 16, src);
        }
    };

    fill(0, 0); CP_COMMIT();

    const int NBLK = SEGTOK / 64;
    for (int kb = 0; kb < NBLK; kb++) {
        __syncthreads();
        if (kb + 1 < NBLK) { fill(kb + 1, (kb + 1) & 1); CP_COMMIT(); CP_WAIT(1); }
        else               { CP_WAIT(0); }
        __syncthreads();

        const uint32_t st = sb + (uint32_t)((kb & 1) * KSTG);

        const __half* ph = (const __half*)(skv + (kb & 1) * KSTG);
        #pragma unroll 8
        for (int r = rg * 32; r < rg * 32 + 32; r++)
            ksl += __half2float(*(const __half*)((const char*)ph + r * KROWB + dloc * 2));

        #pragma unroll
        for (int ks = 0; ks < 4; ks++) {
            const int k0 = ks * 16;
            uint32_t bf[4][2];
            #pragma unroll
            for (int nt = 0; nt < 4; nt++) {
                uint32_t bo = st + KARR + (k0 + bkk) * KROWB + (we * 32 + nt * 8) * 2;
                LDMATRIX_X2_T(bf[nt][0], bf[nt][1], bo);
            }
            #pragma unroll
            for (int mt = 0; mt < 2; mt++) {
                uint32_t af[4];
                uint32_t ao = st + (k0 + akk) * KROWB + (wd * 32 + mt * 16 + amm) * 2;
                LDMATRIX_X4_T(af[0], af[1], af[2], af[3], ao);
                #pragma unroll
                for (int nt = 0; nt < 4; nt++)
                    MMA_F16(acc[mt][nt], af, bf[nt]);
            }
        }
    }

    const int er = lane >> 2, ec = (lane & 3) * 2;
    float* kvb = kvp + ((size_t)seg * B_ * H_ + bh) * D_ * D_;
    #pragma unroll
    for (int mt = 0; mt < 2; mt++)
        #pragma unroll
        for (int nt = 0; nt < 4; nt++) {
            int d = wd * 32 + mt * 16 + er;
            int e = we * 32 + nt * 8 + ec;
            kvb[(e)     * D_ + d]     = acc[mt][nt][0];
            kvb[(e + 1) * D_ + d]     = acc[mt][nt][1];
            kvb[(e)     * D_ + d + 8] = acc[mt][nt][2];
            kvb[(e + 1) * D_ + d + 8] = acc[mt][nt][3];
        }

    sred[rg][dloc] = ksl;
    __syncthreads();
    if (rg == 0) ksp[(seg * B_ * H_ + bh) * D_ + dloc] = sred[0][dloc] + sred[1][dloc];
}

// ---------------- kv partial reduce -> kvT fp16 + ksum -----------------------
__global__ __launch_bounds__(256)
void kv_reduce_kernel(const float* __restrict__ kvp, const float* __restrict__ ksp,
                      __half* __restrict__ kvT, float* __restrict__ ksum)
{
    const int bh = blockIdx.x, tid = threadIdx.x;
    #pragma unroll 4
    for (int i = tid; i < D_ * D_; i += 256) {
        float s = 0.f;
        #pragma unroll
        for (int sg = 0; sg < KVSEG; sg++)
            s += kvp[((size_t)sg * B_ * H_ + bh) * D_ * D_ + i];
        kvT[(size_t)bh * D_ * D_ + i] = __float2half(s);
    }
    if (tid < D_) {
        float s = 0.f;
        #pragma unroll
        for (int sg = 0; sg < KVSEG; sg++)
            s += ksp[(sg * B_ * H_ + bh) * D_ + tid];
        ksum[bh * D_ + tid] = s;
    }
}

// ---------------- attn via mma ----------------
__global__ __launch_bounds__(256)
void attn_mma_kernel(const __half* __restrict__ phiq, const __half* __restrict__ kvT,
                     const float* __restrict__ ksum, __half* __restrict__ attn)
{
    __shared__ __half phq[128 * 72];
    __shared__ __half kvt[64 * 72];
    __shared__ float ksm[64];
    __shared__ float zpart[128][2];
    __shared__ float zb[128];

    const int tid = threadIdx.x, wid = tid >> 5, lane = tid & 31;
    const int bh = blockIdx.x;
    const int n0 = blockIdx.y * 128;
    const int b = bh / H_, h = bh % H_;

    const __half* pq = phiq + ((size_t)bh * NTOK + n0) * D_;
    const __half* kb = kvT + (size_t)bh * D_ * D_;

    #pragma unroll
    for (int i = tid; i < 1024; i += 256) {
        int r = i >> 3, ch = i & 7;
        *(uint4*)&phq[r * 72 + ch * 8] = *(const uint4*)(pq + (size_t)r * D_ + ch * 8);
    }
    #pragma unroll
    for (int i = tid; i < 512; i += 256) {
        int r = i >> 3, ch = i & 7;
        *(uint4*)&kvt[r * 72 + ch * 8] = *(const uint4*)(kb + (size_t)r * D_ + ch * 8);
    }
    if (tid < 64) ksm[tid] = ksum[bh * D_ + tid];
    __syncthreads();

    {
        int row = tid >> 1, hh = tid & 1;
        float z = 0.f;
        #pragma unroll 8
        for (int d = hh * 32; d < hh * 32 + 32; d++)
            z += __half2float(phq[row * 72 + d]) * ksm[d];
        zpart[row][hh] = z;
    }
    __syncthreads();
    if (tid < 128) zb[tid] = 1.f / (zpart[tid][0] + zpart[tid][1] + 1e-5f);

    const int wm2 = (wid & 3) * 32, wn2 = (wid >> 2) * 32;
    const uint32_t pq32 = smem_to_u32(phq), kv32 = smem_to_u32(kvt);
    float acc[2][4][4];
    #pragma unroll
    for (int i = 0; i < 2; i++)
        #pragma unroll
        for (int j = 0; j < 4; j++)
            #pragma unroll
            for (int r = 0; r < 4; r++) acc[i][j][r] = 0.f;

    #pragma unroll
    for (int ks = 0; ks < 4; ks++) {
        const int k0 = ks * 16;
        uint32_t bf[4][2];
        #pragma unroll
        for (int nt = 0; nt < 4; nt++) {
            uint32_t bo = kv32 + (wn2 + nt * 8 + (lane & 7)) * 144 + (k0 + ((lane >> 3) & 1) * 8) * 2;
            LDMATRIX_X2(bf[nt][0], bf[nt][1], bo);
        }
        #pragma unroll
        for (int mt = 0; mt < 2; mt++) {
            uint32_t af[4];
            uint32_t ao = pq32 + (wm2 + mt * 16 + (lane & 15)) * 144 + (k0 + ((lane >> 4) & 1) * 8) * 2;
            LDMATRIX_X4(af[0], af[1], af[2], af[3], ao);
            #pragma unroll
            for (int nt = 0; nt < 4; nt++)
                MMA_F16(acc[mt][nt], af, bf[nt]);
        }
    }
    __syncthreads();

    const int er = lane >> 2, ec = (lane & 3) * 2;
    #pragma unroll
    for (int mt = 0; mt < 2; mt++)
        #pragma unroll
        for (int nt = 0; nt < 4; nt++) {
            int row = wm2 + mt * 16 + er;
            int e   = wn2 + nt * 8 + ec;
            float rz0 = zb[row], rz1 = zb[row + 8];
            size_t base0 = ((size_t)(b * NTOK + n0 + row)) * C_ + h * D_ + e;
            size_t base1 = ((size_t)(b * NTOK + n0 + row + 8)) * C_ + h * D_ + e;
            __half2 o0 = __floats2half2_rn(acc[mt][nt][0] * rz0, acc[mt][nt][1] * rz0);
            __half2 o1 = __floats2half2_rn(acc[mt][nt][2] * rz1, acc[mt][nt][3] * rz1);
            *(__half2*)(attn + base0) = o0;
            *(__half2*)(attn + base1) = o1;
        }
}

// ---------------- fp32 -> fp16 ----------------
__global__ void cvt_h(const float* __restrict__ x, __half* __restrict__ y, int n4)
{
    int i = blockIdx.x * blockDim.x + threadIdx.x;
    if (i >= n4) return;
    float4 f = ((const float4*)x)[i];
    __half h[4];
    h[0] = __float2half(f.x); h[1] = __float2half(f.y);
    h[2] = __float2half(f.z); h[3] = __float2half(f.w);
    ((uint2*)y)[i] = *(uint2*)h;
}

// ---------------- layernorm (fp16 in) -> fp16 --------------------------------
__global__ void ln_kernel(const __half* __restrict__ x,
                          const float* __restrict__ g,
                          const float* __restrict__ b,
                          __half* __restrict__ yh)
{
    int row = blockIdx.x;
    int tid = threadIdx.x; // 256
    const __half* xr = x + (size_t)row * C_;

    float v0 = __half2float(xr[tid]);
    float v1 = __half2float(xr[tid + 256]);
    float v2 = __half2float(xr[tid + 512]);
    float s  = v0 + v1 + v2;
    float ss = v0 * v0 + v1 * v1 + v2 * v2;
#pragma unroll
    for (int o = 16; o > 0; o >>= 1) {
        s  += __shfl_xor_sync(0xffffffffu, s,  o);
        ss += __shfl_xor_sync(0xffffffffu, ss, o);
    }
    __shared__ float ws[8], wss[8];
    int warp = tid >> 5, lane = tid & 31;
    if (lane == 0) { ws[warp] = s; wss[warp] = ss; }
    __syncthreads();
    if (tid == 0) {
        float ts = 0.f, tss = 0.f;
#pragma unroll
        for (int i = 0; i < 8; i++) { ts += ws[i]; tss += wss[i]; }
        ws[0] = ts; wss[0] = tss;
    }
    __syncthreads();
    float mean = ws[0] * (1.f / C_);
    float var  = wss[0] * (1.f / C_) - mean * mean;
    float inv  = rsqrtf(var + 1e-5f);

    size_t rb = (size_t)row * C_;
#pragma unroll
    for (int j = 0; j < 3; j++) {
        int c = tid + j * 256;
        float vv = (j == 0 ? v0 : (j == 1 ? v1 : v2));
        float y = (vv - mean) * inv * g[c] + b[c];
        yh[rb + c] = __float2half(y);
    }
}

// ---------------- launch ------------------------------------------------------
extern "C" void kernel_launch(void* const* d_in, const int* in_sizes, int n_in,
                              void* d_out, int out_size)
{
    (void)in_sizes; (void)n_in; (void)out_size;
    const float* x      = (const float*)d_in[0];
    const float* rope   = (const float*)d_in[1];
    const float* qkv_w  = (const float*)d_in[2];
    const float* q_bias = (const float*)d_in[3];
    const float* v_bias = (const float*)d_in[4];
    const float* norm_g = (const float*)d_in[5];
    const float* norm_b = (const float*)d_in[6];
    const float* proj_w = (const float*)d_in[7];
    const float* proj_b = (const float*)d_in[8];
    float* out = (float*)d_out;

    float *ksum, *kvp, *ksp;
    __half *phiq, *phik, *v, *kvT, *attn, *xh, *w, *pw, *lh;
    cudaGetSymbolAddress((void**)&phiq, g_phiq);
    cudaGetSymbolAddress((void**)&phik, g_phik);
    cudaGetSymbolAddress((void**)&v,    g_v);
    cudaGetSymbolAddress((void**)&kvT,  g_kvT);
    cudaGetSymbolAddress((void**)&kvp,  g_kvp);
    cudaGetSymbolAddress((void**)&ksum, g_ksum);
    cudaGetSymbolAddress((void**)&ksp,  g_ksp);
    cudaGetSymbolAddress((void**)&attn, g_attn);
    cudaGetSymbolAddress((void**)&xh,   g_xh);
    cudaGetSymbolAddress((void**)&w,    g_w);
    cudaGetSymbolAddress((void**)&pw,   g_pw);
    cudaGetSymbolAddress((void**)&lh,   g_lh);

    cudaFuncSetAttribute(mma_gemm_qkv,  cudaFuncAttributeMaxDynamicSharedMemorySize, SMEM_GEMM);
    cudaFuncSetAttribute(mma_gemm_proj, cudaFuncAttributeMaxDynamicSharedMemorySize, SMEM_GEMM);

    // 0) conversions
    {
        int n4 = (M_ * KDIM) / 4;
        cvt_h<<<(n4 + 255) / 256, 256>>>(x, xh, n4);
        n4 = (QKVN * KDIM) / 4;
        cvt_h<<<(n4 + 255) / 256, 256>>>(qkv_w, w, n4);
        n4 = (C_ * KDIM) / 4;
        cvt_h<<<(n4 + 255) / 256, 256>>>(proj_w, pw, n4);
    }

    // 1) fused qkv GEMM + bias + rope + softmax + head-scatter (fp16 out)
    mma_gemm_qkv<<<dim3(QKVN / BN, M_ / BM), 256, SMEM_GEMM>>>(
        xh, w, rope, q_bias, v_bias, phiq, phik, v);

    // 2) kv partials via tensor cores (4-way token split), then reduce
    kv_mma_kernel<<<dim3(B_ * H_, KVSEG), 128>>>(phik, v, kvp, ksp);
    kv_reduce_kernel<<<B_ * H_, 256>>>(kvp, ksp, kvT, ksum);

    // 3) attention output via tensor cores
    attn_mma_kernel<<<dim3(B_ * H_, NTOK / 128), 256>>>(phiq, kvT, ksum, attn);

    // 4) layernorm (fp16 -> fp16)
    ln_kernel<<<M_, 256>>>(attn, norm_g, norm_b, lh);

    // 5) out = ln @ proj_w^T + proj_b
    mma_gemm_proj<<<dim3(C_ / BN, M_ / BM), 256, SMEM_GEMM>>>(
        lh, pw, out, C_, proj_b);
}

// round 15
// speedup vs baseline: 1.5208x; 1.0142x over previous
#include <cuda_runtime.h>
#include <cuda_fp16.h>
#include <cstdint>

// ---------------- problem constants ----------------
#define B_    8
#define NTOK  4096
#define C_    768
#define H_    12
#define D_    64
#define M_    (B_ * NTOK)     // 32768
#define QKVN  (3 * C_)        // 2304
#define KDIM  768
#define KVSEG 4               // kv split segments

// ---------------- scratch (device globals) ----------------
__device__ __half g_phiq[(size_t)B_ * H_ * NTOK * D_];
__device__ __half g_phik[(size_t)B_ * H_ * NTOK * D_];
__device__ __half g_v   [(size_t)B_ * H_ * NTOK * D_];
__device__ __half g_kvT [B_ * H_ * D_ * D_];          // [bh][e][d]
__device__ float  g_kvp [KVSEG * B_ * H_ * D_ * D_];  // fp32 partials
__device__ float  g_ksum[B_ * H_ * D_];
__device__ float  g_ksp [KVSEG * B_ * H_ * D_];
__device__ __half g_attn[(size_t)M_ * C_];

__device__ __half g_xh [(size_t)M_ * KDIM];
__device__ __half g_w  [(size_t)QKVN * KDIM];
__device__ __half g_pw [(size_t)C_ * KDIM];
__device__ __half g_lh [(size_t)M_ * KDIM];

// ---------------- low-level helpers ----------------
__device__ __forceinline__ uint32_t smem_to_u32(const void* p) {
    uint32_t a;
    asm("{ .reg .u64 t; cvta.to.shared.u64 t, %1; cvt.u32.u64 %0, t; }"
        : "=r"(a) : "l"(p));
    return a;
}

#define CP_ASYNC_CG(dst, src) \
    asm volatile("cp.async.cg.shared.global [%0], [%1], 16;" :: "r"(dst), "l"(src))
#define CP_COMMIT()  asm volatile("cp.async.commit_group;" ::: "memory")
#define CP_WAIT(N)   asm volatile("cp.async.wait_group %0;" :: "n"(N) : "memory")

#define LDMATRIX_X4(r0, r1, r2, r3, addr) \
    asm volatile("ldmatrix.sync.aligned.m8n8.x4.shared.b16 {%0,%1,%2,%3}, [%4];" \
        : "=r"(r0), "=r"(r1), "=r"(r2), "=r"(r3) : "r"(addr))
#define LDMATRIX_X2(r0, r1, addr) \
    asm volatile("ldmatrix.sync.aligned.m8n8.x2.shared.b16 {%0,%1}, [%2];" \
        : "=r"(r0), "=r"(r1) : "r"(addr))
#define LDMATRIX_X4_T(r0, r1, r2, r3, addr) \
    asm volatile("ldmatrix.sync.aligned.m8n8.x4.trans.shared.b16 {%0,%1,%2,%3}, [%4];" \
        : "=r"(r0), "=r"(r1), "=r"(r2), "=r"(r3) : "r"(addr))
#define LDMATRIX_X2_T(r0, r1, addr) \
    asm volatile("ldmatrix.sync.aligned.m8n8.x2.trans.shared.b16 {%0,%1}, [%2];" \
        : "=r"(r0), "=r"(r1) : "r"(addr))

#define MMA_F16(d, a, b) \
    asm volatile("mma.sync.aligned.m16n8k16.row.col.f32.f16.f16.f32 " \
        "{%0,%1,%2,%3}, {%4,%5,%6,%7}, {%8,%9}, {%0,%1,%2,%3};" \
        : "+f"((d)[0]), "+f"((d)[1]), "+f"((d)[2]), "+f"((d)[3]) \
        : "r"((a)[0]), "r"((a)[1]), "r"((a)[2]), "r"((a)[3]), \
          "r"((b)[0]), "r"((b)[1]))

// ---------------- GEMM tiling (R12/13 proven: 8 warps 64x32, prefetch 2) ----
#define BM 128
#define BN 128
#define BKB 32
#define KB  (KDIM / BKB)         // 24
#define ROWB 80
#define ARR_BYTES (128 * ROWB)
#define STAGE (2 * ARR_BYTES)
#define NSTG 4
#define SMEM_GEMM (NSTG * STAGE) // 81920

__device__ __forceinline__ void gemm_mainloop(
    const __half* __restrict__ A, const __half* __restrict__ Bw,
    int bm, int bn, uint32_t sb, int tid, int wid, int lane,
    float acc[4][4][4])
{
    const int wm = (wid & 1) * 64;
    const int wn = (wid >> 1) * 32;

    const int lrow = tid >> 2;
    const int lch  = tid & 3;
    const __half* srcs[4];
    uint32_t dsts[4];
    {
        const __half* bases[2] = { A, Bw };
        #pragma unroll
        for (int i = 0; i < 4; i++) {
            int arr = i >> 1;
            int row = (i & 1) * 64 + lrow;
            int roff = (arr == 0) ? (bm + row) : (bn + row);
            srcs[i] = bases[arr] + (size_t)roff * KDIM + lch * 8;
            dsts[i] = sb + arr * ARR_BYTES + row * ROWB + lch * 16;
        }
    }

    const uint32_t a_row  = (uint32_t)(wm + (lane & 15));
    const uint32_t a_colb = (uint32_t)(((lane >> 4) & 1) * 16);
    const uint32_t b_row4 = (uint32_t)(wn + ((lane >> 4) & 1) * 8 + (lane & 7));
    const uint32_t b_col4 = (uint32_t)(((lane >> 3) & 1) * 16);

    #pragma unroll
    for (int i = 0; i < 4; i++)
        #pragma unroll
        for (int j = 0; j < 4; j++)
            #pragma unroll
            for (int r = 0; r < 4; r++) acc[i][j][r] = 0.f;

    // preload stages 0,1 (prefetch distance 2 — PROVEN SAFE:
    // fill target (kb+2)&3 is disjoint from current readers kb&3 AND from
    // lagging epoch-(kb-1) readers (kb-1)&3 == (kb+3)&3)
    #pragma unroll
    for (int p = 0; p < 2; p++) {
        const uint32_t so = (uint32_t)(p * STAGE);
        const int k0 = p * BKB;
        #pragma unroll
        for (int i = 0; i < 4; i++) CP_ASYNC_CG(dsts[i] + so, srcs[i] + k0);
        CP_COMMIT();
    }

    for (int kb = 0; kb < KB; kb++) {
        const int pf = kb + 2;
        if (pf < KB) {
            const uint32_t so = (uint32_t)((pf & (NSTG - 1)) * STAGE);
            const int k0 = pf * BKB;
            #pragma unroll
            for (int i = 0; i < 4; i++) CP_ASYNC_CG(dsts[i] + so, srcs[i] + k0);
        }
        CP_COMMIT();
        CP_WAIT(2);
        __syncthreads();

        const uint32_t st = sb + (uint32_t)((kb & (NSTG - 1)) * STAGE);
        #pragma unroll
        for (int ks = 0; ks < 2; ks++) {
            const uint32_t kB = (uint32_t)(ks * 32);
            uint32_t bf[4][2];
            #pragma unroll
            for (int pr = 0; pr < 2; pr++) {
                uint32_t bo = st + ARR_BYTES + (b_row4 + pr * 16) * ROWB + kB + b_col4;
                LDMATRIX_X4(bf[2 * pr][0], bf[2 * pr][1],
                            bf[2 * pr + 1][0], bf[2 * pr + 1][1], bo);
            }
            #pragma unroll
            for (int mt = 0; mt < 4; mt++) {
                uint32_t af[4];
                uint32_t ao = st + (a_row + mt * 16) * ROWB + kB + a_colb;
                LDMATRIX_X4(af[0], af[1], af[2], af[3], ao);
                #pragma unroll
                for (int nt = 0; nt < 4; nt++)
                    MMA_F16(acc[mt][nt], af, bf[nt]);
            }
        }
    }
}

// ---------------- GEMM1: qkv with fused bias+rope+softmax+scatter ----------
#define EPS 132

__global__ __launch_bounds__(256, 2)
void mma_gemm_qkv(const __half* __restrict__ A, const __half* __restrict__ Bw,
                  const float* __restrict__ rope,
                  const float* __restrict__ q_bias, const float* __restrict__ v_bias,
                  __half* __restrict__ phiq, __half* __restrict__ phik, __half* __restrict__ vout)
{
    extern __shared__ char smem[];
    const uint32_t sb = smem_to_u32(smem);
    const int tid = threadIdx.x, wid = tid >> 5, lane = tid & 31;
    const int bm = blockIdx.y * BM, bn = blockIdx.x * BN;

    float acc[4][4][4];
    gemm_mainloop(A, Bw, bm, bn, sb, tid, wid, lane, acc);
    __syncthreads();

    float* epi = (float*)smem;
    const int wm = (wid & 1) * 64, wn = (wid >> 1) * 32;
    const int er = lane >> 2, ec = (lane & 3) * 2;
    #pragma unroll
    for (int mt = 0; mt < 4; mt++)
        #pragma unroll
        for (int nt = 0; nt < 4; nt++) {
            int r0 = wm + mt * 16 + er, c = wn + nt * 8 + ec;
            *(float2*)&epi[r0 * EPS + c]       = make_float2(acc[mt][nt][0], acc[mt][nt][1]);
            *(float2*)&epi[(r0 + 8) * EPS + c] = make_float2(acc[mt][nt][2], acc[mt][nt][3]);
        }
    __syncthreads();

    const int region = bn / C_;
    const int col0   = bn - region * C_;
    const float* bias = (region == 0) ? q_bias : (region == 2 ? v_bias : nullptr);
    __half* outbuf = (region == 0) ? phiq : (region == 1 ? phik : vout);

    const int sub    = lane >> 4;
    const int lane15 = lane & 15;
    const int g      = lane15 >> 3;
    const int dof    = (lane15 & 7) << 3;
    const int h      = (col0 >> 6) + g;

    #pragma unroll 2
    for (int rr = 0; rr < 8; rr++) {
        const int row  = wid * 16 + rr * 2 + sub;
        const int gtok = bm + row;
        const int b    = gtok >> 12;
        const int n    = gtok & (NTOK - 1);

        float4 v0 = *(float4*)&epi[row * EPS + g * 64 + dof];
        float4 v1 = *(float4*)&epi[row * EPS + g * 64 + dof + 4];
        float vals[8] = { v0.x, v0.y, v0.z, v0.w, v1.x, v1.y, v1.z, v1.w };

        if (bias) {
            #pragma unroll
            for (int j = 0; j < 8; j++) vals[j] += bias[col0 + g * 64 + dof + j];
        }

        if (region != 2) {
            if (n >= 1) {
                const float* rp = rope + (size_t)(n - 1) * (2 * D_) + dof;
                float4 s0 = *(const float4*)rp;
                float4 s1 = *(const float4*)(rp + 4);
                float4 c0 = *(const float4*)(rp + 64);
                float4 c1 = *(const float4*)(rp + 68);
                float snv[8] = { s0.x, s0.y, s0.z, s0.w, s1.x, s1.y, s1.z, s1.w };
                float csv[8] = { c0.x, c0.y, c0.z, c0.w, c1.x, c1.y, c1.z, c1.w };
                #pragma unroll
                for (int p = 0; p < 4; p++) {
                    float t0 = vals[2 * p], t1 = vals[2 * p + 1];
                    vals[2 * p]     = t0 * csv[2 * p]     - t1 * snv[2 * p];
                    vals[2 * p + 1] = t1 * csv[2 * p + 1] + t0 * snv[2 * p + 1];
                }
            }
            float m = vals[0];
            #pragma unroll
            for (int j = 1; j < 8; j++) m = fmaxf(m, vals[j]);
            #pragma unroll
            for (int o = 1; o < 8; o <<= 1)
                m = fmaxf(m, __shfl_xor_sync(0xffffffffu, m, o));
            float s = 0.f;
            #pragma unroll
            for (int j = 0; j < 8; j++) { vals[j] = expf(vals[j] - m); s += vals[j]; }
            #pragma unroll
            for (int o = 1; o < 8; o <<= 1)
                s += __shfl_xor_sync(0xffffffffu, s, o);
            float rs = 1.f / s;
            #pragma unroll
            for (int j = 0; j < 8; j++) vals[j] *= rs;
        }

        __half hv[8];
        #pragma unroll
        for (int j = 0; j < 8; j++) hv[j] = __float2half(vals[j]);
        __half* dst = outbuf + (((size_t)b * H_ + h) * NTOK + n) * D_ + dof;
        *(uint4*)dst = *(uint4*)hv;
    }
}

// ---------------- GEMM2: proj with bias ----------------
__global__ __launch_bounds__(256, 2)
void mma_gemm_proj(const __half* __restrict__ A, const __half* __restrict__ Bw,
                   float* __restrict__ Cc, int N, const float* __restrict__ bias_full)
{
    extern __shared__ char smem[];
    const uint32_t sb = smem_to_u32(smem);
    const int tid = threadIdx.x, wid = tid >> 5, lane = tid & 31;
    const int bm = blockIdx.y * BM, bn = blockIdx.x * BN;

    float acc[4][4][4];
    gemm_mainloop(A, Bw, bm, bn, sb, tid, wid, lane, acc);

    const int wm = (wid & 1) * 64, wn = (wid >> 1) * 32;
    const int er = lane >> 2, ec = (lane & 3) * 2;
    #pragma unroll
    for (int mt = 0; mt < 4; mt++) {
        #pragma unroll
        for (int nt = 0; nt < 4; nt++) {
            int row = bm + wm + mt * 16 + er;
            int col = bn + wn + nt * 8 + ec;
            float b0 = bias_full[col], b1 = bias_full[col + 1];
            *(float2*)(Cc + (size_t)row * N + col) =
                make_float2(acc[mt][nt][0] + b0, acc[mt][nt][1] + b1);
            *(float2*)(Cc + (size_t)(row + 8) * N + col) =
                make_float2(acc[mt][nt][2] + b0, acc[mt][nt][3] + b1);
        }
    }
}

// ---------------- kv via mma, 4-way split over tokens ----------------
#define KROWB 144
#define KARR  (64 * KROWB)
#define KSTG  (2 * KARR)
#define SEGTOK (NTOK / KVSEG)

__global__ __launch_bounds__(128)
void kv_mma_kernel(const __half* __restrict__ phik, const __half* __restrict__ v,
                   float* __restrict__ kvp, float* __restrict__ ksp)
{
    __shared__ char skv[2 * KSTG];
    const uint32_t sb = smem_to_u32(skv);
    const int tid = threadIdx.x, wid = tid >> 5, lane = tid & 31;
    const int bh = blockIdx.x;
    const int seg = blockIdx.y;
    const int nbase = seg * SEGTOK;

    const __half* pk = phik + (size_t)bh * NTOK * D_;
    const __half* pv = v    + (size_t)bh * NTOK * D_;

    const int wd = wid & 1, we = wid >> 1;

    const int akk = (lane & 7) + ((lane >> 4) & 1) * 8;
    const int amm = ((lane >> 3) & 1) * 8;
    const int bkk = (lane & 7) + ((lane >> 3) & 1) * 8;

    float acc[2][4][4];
    #pragma unroll
    for (int i = 0; i < 2; i++)
        #pragma unroll
        for (int j = 0; j < 4; j++)
            #pragma unroll
            for (int r = 0; r < 4; r++) acc[i][j][r] = 0.f;

    float2 ksl2 = make_float2(0.f, 0.f);
    const int dpair = tid & 31;     // half2 pair index (d = 2*dpair)
    const int rg = tid >> 5;        // 4 row groups of 16

    auto fill = [&](int kb, int slot) {
        const int n0 = nbase + kb * 64;
        const uint32_t so = sb + (uint32_t)(slot * KSTG);
        #pragma unroll
        for (int i = tid; i < 1024; i += 128) {
            int arr = i >> 9;
            int r   = (i >> 3) & 63;
            int ch  = i & 7;
            const __half* src = (arr ? pv : pk) + (size_t)(n0 + r) * D_ + ch * 8;
            CP_ASYNC_CG(so + arr * KARR + r * KROWB + ch * 16, src);
        }
    };

    fill(0, 0); CP_COMMIT();

    const int NBLK = SEGTOK / 64;
    for (int kb = 0; kb < NBLK; kb++) {
        __syncthreads();
        if (kb + 1 < NBLK) { fill(kb + 1, (kb + 1) & 1); CP_COMMIT(); CP_WAIT(1); }
        else               { CP_WAIT(0); }
        __syncthreads();

        const uint32_t st = sb + (uint32_t)((kb & 1) * KSTG);

        // ksum partial via half2 loads (16 vector LDS per thread)
        const char* ph = skv + (kb & 1) * KSTG;
        #pragma unroll 16
        for (int r = rg * 16; r < rg * 16 + 16; r++) {
            __half2 kk = *(const __half2*)(ph + r * KROWB + dpair * 4);
            float2 kf = __half22float2(kk);
            ksl2.x += kf.x; ksl2.y += kf.y;
        }

        #pragma unroll
        for (int ks = 0; ks < 4; ks++) {
            const int k0 = ks * 16;
            uint32_t bf[4][2];
            #pragma unroll
            for (int nt = 0; nt < 4; nt++) {
                uint32_t bo = st + KARR + (k0 + bkk) * KROWB + (we * 32 + nt * 8) * 2;
                LDMATRIX_X2_T(bf[nt][0], bf[nt][1], bo);
            }
            #pragma unroll
            for (int mt = 0; mt < 2; mt++) {
                uint32_t af[4];
                uint32_t ao = st + (k0 + akk) * KROWB + (wd * 32 + mt * 16 + amm) * 2;
                LDMATRIX_X4_T(af[0], af[1], af[2], af[3], ao);
                #pragma unroll
                for (int nt = 0; nt < 4; nt++)
                    MMA_F16(acc[mt][nt], af, bf[nt]);
            }
        }
    }

    const int er = lane >> 2, ec = (lane & 3) * 2;
    float* kvb = kvp + ((size_t)seg * B_ * H_ + bh) * D_ * D_;
    #pragma unroll
    for (int mt = 0; mt < 2; mt++)
        #pragma unroll
        for (int nt = 0; nt < 4; nt++) {
            int d = wd * 32 + mt * 16 + er;
            int e = we * 32 + nt * 8 + ec;
            kvb[(e)     * D_ + d]     = acc[mt][nt][0];
            kvb[(e + 1) * D_ + d]     = acc[mt][nt][1];
            kvb[(e)     * D_ + d + 8] = acc[mt][nt][2];
            kvb[(e + 1) * D_ + d + 8] = acc[mt][nt][3];
        }

    __shared__ float kred[4][64];
    kred[rg][2 * dpair]     = ksl2.x;
    kred[rg][2 * dpair + 1] = ksl2.y;
    __syncthreads();
    if (tid < 64) {
        float s = kred[0][tid] + kred[1][tid] + kred[2][tid] + kred[3][tid];
        ksp[(seg * B_ * H_ + bh) * D_ + tid] = s;
    }
}

// ---------------- kv partial reduce -> kvT fp16 + ksum -----------------------
__global__ __launch_bounds__(256)
void kv_reduce_kernel(const float* __restrict__ kvp, const float* __restrict__ ksp,
                      __half* __restrict__ kvT, float* __restrict__ ksum)
{
    const int bh = blockIdx.x, tid = threadIdx.x;
    #pragma unroll 4
    for (int i = tid; i < D_ * D_; i += 256) {
        float s = 0.f;
        #pragma unroll
        for (int sg = 0; sg < KVSEG; sg++)
            s += kvp[((size_t)sg * B_ * H_ + bh) * D_ * D_ + i];
        kvT[(size_t)bh * D_ * D_ + i] = __float2half(s);
    }
    if (tid < D_) {
        float s = 0.f;
        #pragma unroll
        for (int sg = 0; sg < KVSEG; sg++)
            s += ksp[(sg * B_ * H_ + bh) * D_ + tid];
        ksum[bh * D_ + tid] = s;
    }
}

// ---------------- attn via mma (coalesced smem-staged epilogue) -------------
__global__ __launch_bounds__(256)
void attn_mma_kernel(const __half* __restrict__ phiq, const __half* __restrict__ kvT,
                     const float* __restrict__ ksum, __half* __restrict__ attn)
{
    __shared__ __half phq[128 * 72];     // input tile; reused as output stage
    __shared__ __half kvt[64 * 72];
    __shared__ float ksm[64];
    __shared__ float zpart[128][2];
    __shared__ float zb[128];

    const int tid = threadIdx.x, wid = tid >> 5, lane = tid & 31;
    const int bh = blockIdx.x;
    const int n0 = blockIdx.y * 128;
    const int b = bh / H_, h = bh % H_;

    const __half* pq = phiq + ((size_t)bh * NTOK + n0) * D_;
    const __half* kb = kvT + (size_t)bh * D_ * D_;

    #pragma unroll
    for (int i = tid; i < 1024; i += 256) {
        int r = i >> 3, ch = i & 7;
        *(uint4*)&phq[r * 72 + ch * 8] = *(const uint4*)(pq + (size_t)r * D_ + ch * 8);
    }
    #pragma unroll
    for (int i = tid; i < 512; i += 256) {
        int r = i >> 3, ch = i & 7;
        *(uint4*)&kvt[r * 72 + ch * 8] = *(const uint4*)(kb + (size_t)r * D_ + ch * 8);
    }
    if (tid < 64) ksm[tid] = ksum[bh * D_ + tid];
    __syncthreads();

    {
        int row = tid >> 1, hh = tid & 1;
        float z = 0.f;
        #pragma unroll 8
        for (int d = hh * 32; d < hh * 32 + 32; d++)
            z += __half2float(phq[row * 72 + d]) * ksm[d];
        zpart[row][hh] = z;
    }
    __syncthreads();
    if (tid < 128) zb[tid] = 1.f / (zpart[tid][0] + zpart[tid][1] + 1e-5f);

    const int wm2 = (wid & 3) * 32, wn2 = (wid >> 2) * 32;
    const uint32_t pq32 = smem_to_u32(phq), kv32 = smem_to_u32(kvt);
    float acc[2][4][4];
    #pragma unroll
    for (int i = 0; i < 2; i++)
        #pragma unroll
        for (int j = 0; j < 4; j++)
            #pragma unroll
            for (int r = 0; r < 4; r++) acc[i][j][r] = 0.f;

    #pragma unroll
    for (int ks = 0; ks < 4; ks++) {
        const int k0 = ks * 16;
        uint32_t bf[4][2];
        #pragma unroll
        for (int nt = 0; nt < 4; nt++) {
            uint32_t bo = kv32 + (wn2 + nt * 8 + (lane & 7)) * 144 + (k0 + ((lane >> 3) & 1) * 8) * 2;
            LDMATRIX_X2(bf[nt][0], bf[nt][1], bo);
        }
        #pragma unroll
        for (int mt = 0; mt < 2; mt++) {
            uint32_t af[4];
            uint32_t ao = pq32 + (wm2 + mt * 16 + (lane & 15)) * 144 + (k0 + ((lane >> 4) & 1) * 8) * 2;
            LDMATRIX_X4(af[0], af[1], af[2], af[3], ao);
            #pragma unroll
            for (int nt = 0; nt < 4; nt++)
                MMA_F16(acc[mt][nt], af, bf[nt]);
        }
    }
    __syncthreads();   // all phq reads done; zb ready; safe to reuse phq

    const int er = lane >> 2, ec = (lane & 3) * 2;
    #pragma unroll
    for (int mt = 0; mt < 2; mt++)
        #pragma unroll
        for (int nt = 0; nt < 4; nt++) {
            int row = wm2 + mt * 16 + er;
            int e   = wn2 + nt * 8 + ec;
            float rz0 = zb[row], rz1 = zb[row + 8];
            *(__half2*)&phq[row * 72 + e] =
                __floats2half2_rn(acc[mt][nt][0] * rz0, acc[mt][nt][1] * rz0);
            *(__half2*)&phq[(row + 8) * 72 + e] =
                __floats2half2_rn(acc[mt][nt][2] * rz1, acc[mt][nt][3] * rz1);
        }
    __syncthreads();

    #pragma unroll
    for (int i = tid; i < 1024; i += 256) {
        int row = i >> 3, ch = i & 7;
        __half* dst = attn + ((size_t)(b * NTOK + n0 + row)) * C_ + h * D_ + ch * 8;
        *(uint4*)dst = *(uint4*)&phq[row * 72 + ch * 8];
    }
}

// ---------------- fp32 -> fp16 ----------------
__global__ void cvt_h(const float* __restrict__ x, __half* __restrict__ y, int n4)
{
    int i = blockIdx.x * blockDim.x + threadIdx.x;
    if (i >= n4) return;
    float4 f = ((const float4*)x)[i];
    __half h[4];
    h[0] = __float2half(f.x); h[1] = __float2half(f.y);
    h[2] = __float2half(f.z); h[3] = __float2half(f.w);
    ((uint2*)y)[i] = *(uint2*)h;
}

// ---------------- layernorm (fp16 in) -> fp16 --------------------------------
__global__ void ln_kernel(const __half* __restrict__ x,
                          const float* __restrict__ g,
                          const float* __restrict__ b,
                          __half* __restrict__ yh)
{
    int row = blockIdx.x;
    int tid = threadIdx.x; // 256
    const __half* xr = x + (size_t)row * C_;

    float v0 = __half2float(xr[tid]);
    float v1 = __half2float(xr[tid + 256]);
    float v2 = __half2float(xr[tid + 512]);
    float s  = v0 + v1 + v2;
    float ss = v0 * v0 + v1 * v1 + v2 * v2;
#pragma unroll
    for (int o = 16; o > 0; o >>= 1) {
        s  += __shfl_xor_sync(0xffffffffu, s,  o);
        ss += __shfl_xor_sync(0xffffffffu, ss, o);
    }
    __shared__ float ws[8], wss[8];
    int warp = tid >> 5, lane = tid & 31;
    if (lane == 0) { ws[warp] = s; wss[warp] = ss; }
    __syncthreads();
    if (tid == 0) {
        float ts = 0.f, tss = 0.f;
#pragma unroll
        for (int i = 0; i < 8; i++) { ts += ws[i]; tss += wss[i]; }
        ws[0] = ts; wss[0] = tss;
    }
    __syncthreads();
    float mean = ws[0] * (1.f / C_);
    float var  = wss[0] * (1.f / C_) - mean * mean;
    float inv  = rsqrtf(var + 1e-5f);

    size_t rb = (size_t)row * C_;
#pragma unroll
    for (int j = 0; j < 3; j++) {
        int c = tid + j * 256;
        float vv = (j == 0 ? v0 : (j == 1 ? v1 : v2));
        float y = (vv - mean) * inv * g[c] + b[c];
        yh[rb + c] = __float2half(y);
    }
}

// ---------------- launch ------------------------------------------------------
extern "C" void kernel_launch(void* const* d_in, const int* in_sizes, int n_in,
                              void* d_out, int out_size)
{
    (void)in_sizes; (void)n_in; (void)out_size;
    const float* x      = (const float*)d_in[0];
    const float* rope   = (const float*)d_in[1];
    const float* qkv_w  = (const float*)d_in[2];
    const float* q_bias = (const float*)d_in[3];
    const float* v_bias = (const float*)d_in[4];
    const float* norm_g = (const float*)d_in[5];
    const float* norm_b = (const float*)d_in[6];
    const float* proj_w = (const float*)d_in[7];
    const float* proj_b = (const float*)d_in[8];
    float* out = (float*)d_out;

    float *ksum, *kvp, *ksp;
    __half *phiq, *phik, *v, *kvT, *attn, *xh, *w, *pw, *lh;
    cudaGetSymbolAddress((void**)&phiq, g_phiq);
    cudaGetSymbolAddress((void**)&phik, g_phik);
    cudaGetSymbolAddress((void**)&v,    g_v);
    cudaGetSymbolAddress((void**)&kvT,  g_kvT);
    cudaGetSymbolAddress((void**)&kvp,  g_kvp);
    cudaGetSymbolAddress((void**)&ksum, g_ksum);
    cudaGetSymbolAddress((void**)&ksp,  g_ksp);
    cudaGetSymbolAddress((void**)&attn, g_attn);
    cudaGetSymbolAddress((void**)&xh,   g_xh);
    cudaGetSymbolAddress((void**)&w,    g_w);
    cudaGetSymbolAddress((void**)&pw,   g_pw);
    cudaGetSymbolAddress((void**)&lh,   g_lh);

    cudaFuncSetAttribute(mma_gemm_qkv,  cudaFuncAttributeMaxDynamicSharedMemorySize, SMEM_GEMM);
    cudaFuncSetAttribute(mma_gemm_proj, cudaFuncAttributeMaxDynamicSharedMemorySize, SMEM_GEMM);

    // 0) conversions
    {
        int n4 = (M_ * KDIM) / 4;
        cvt_h<<<(n4 + 255) / 256, 256>>>(x, xh, n4);
        n4 = (QKVN * KDIM) / 4;
        cvt_h<<<(n4 + 255) / 256, 256>>>(qkv_w, w, n4);
        n4 = (C_ * KDIM) / 4;
        cvt_h<<<(n4 + 255) / 256, 256>>>(proj_w, pw, n4);
    }

    // 1) fused qkv GEMM + bias + rope + softmax + head-scatter (fp16 out)
    mma_gemm_qkv<<<dim3(QKVN / BN, M_ / BM), 256, SMEM_GEMM>>>(
        xh, w, rope, q_bias, v_bias, phiq, phik, v);

    // 2) kv partials via tensor cores (4-way token split), then reduce
    kv_mma_kernel<<<dim3(B_ * H_, KVSEG), 128>>>(phik, v, kvp, ksp);
    kv_reduce_kernel<<<B_ * H_, 256>>>(kvp, ksp, kvT, ksum);

    // 3) attention output via tensor cores (coalesced stores)
    attn_mma_kernel<<<dim3(B_ * H_, NTOK / 128), 256>>>(phiq, kvT, ksum, attn);

    // 4) layernorm (fp16 -> fp16)
    ln_kernel<<<M_, 256>>>(attn, norm_g, norm_b, lh);

    // 5) out = ln @ proj_w^T + proj_b
    mma_gemm_proj<<<dim3(C_ / BN, M_ / BM), 256, SMEM_GEMM>>>(
        lh, pw, out, C_, proj_b);
}

// round 16
// speedup vs baseline: 1.5816x; 1.0400x over previous
#include <cuda_runtime.h>
#include <cuda_fp16.h>
#include <cstdint>

// ---------------- problem constants ----------------
#define B_    8
#define NTOK  4096
#define C_    768
#define H_    12
#define D_    64
#define M_    (B_ * NTOK)     // 32768
#define QKVN  (3 * C_)        // 2304
#define KDIM  768
#define KVSEG 4

// ---------------- scratch (device globals) ----------------
__device__ __half g_phiq[(size_t)B_ * H_ * NTOK * D_];
__device__ __half g_phik[(size_t)B_ * H_ * NTOK * D_];
__device__ __half g_v   [(size_t)B_ * H_ * NTOK * D_];
__device__ __half g_kvT [B_ * H_ * D_ * D_];
__device__ float  g_kvp [KVSEG * B_ * H_ * D_ * D_];
__device__ float  g_ksum[B_ * H_ * D_];
__device__ float  g_ksp [KVSEG * B_ * H_ * D_];
__device__ __half g_attn[(size_t)M_ * C_];

__device__ __half g_xh [(size_t)M_ * KDIM];
__device__ __half g_w  [(size_t)QKVN * KDIM];
__device__ __half g_pw [(size_t)C_ * KDIM];    // g-folded proj weights
__device__ float  g_rstd[M_];                  // 1/sqrt(var+eps) per row
__device__ float  g_rm [M_];                   // rstd*mean per row
__device__ float  g_u  [C_];                   // sum_k g[k]W[n,k]
__device__ float  g_tb [C_];                   // sum_k b[k]W[n,k] + proj_b[n]

// ---------------- low-level helpers ----------------
__device__ __forceinline__ uint32_t smem_to_u32(const void* p) {
    uint32_t a;
    asm("{ .reg .u64 t; cvta.to.shared.u64 t, %1; cvt.u32.u64 %0, t; }"
        : "=r"(a) : "l"(p));
    return a;
}

#define CP_ASYNC_CG(dst, src) \
    asm volatile("cp.async.cg.shared.global [%0], [%1], 16;" :: "r"(dst), "l"(src))
#define CP_COMMIT()  asm volatile("cp.async.commit_group;" ::: "memory")
#define CP_WAIT(N)   asm volatile("cp.async.wait_group %0;" :: "n"(N) : "memory")

#define LDMATRIX_X4(r0, r1, r2, r3, addr) \
    asm volatile("ldmatrix.sync.aligned.m8n8.x4.shared.b16 {%0,%1,%2,%3}, [%4];" \
        : "=r"(r0), "=r"(r1), "=r"(r2), "=r"(r3) : "r"(addr))
#define LDMATRIX_X2(r0, r1, addr) \
    asm volatile("ldmatrix.sync.aligned.m8n8.x2.shared.b16 {%0,%1}, [%2];" \
        : "=r"(r0), "=r"(r1) : "r"(addr))
#define LDMATRIX_X4_T(r0, r1, r2, r3, addr) \
    asm volatile("ldmatrix.sync.aligned.m8n8.x4.trans.shared.b16 {%0,%1,%2,%3}, [%4];" \
        : "=r"(r0), "=r"(r1), "=r"(r2), "=r"(r3) : "r"(addr))
#define LDMATRIX_X2_T(r0, r1, addr) \
    asm volatile("ldmatrix.sync.aligned.m8n8.x2.trans.shared.b16 {%0,%1}, [%2];" \
        : "=r"(r0), "=r"(r1) : "r"(addr))

#define MMA_F16(d, a, b) \
    asm volatile("mma.sync.aligned.m16n8k16.row.col.f32.f16.f16.f32 " \
        "{%0,%1,%2,%3}, {%4,%5,%6,%7}, {%8,%9}, {%0,%1,%2,%3};" \
        : "+f"((d)[0]), "+f"((d)[1]), "+f"((d)[2]), "+f"((d)[3]) \
        : "r"((a)[0]), "r"((a)[1]), "r"((a)[2]), "r"((a)[3]), \
          "r"((b)[0]), "r"((b)[1]))

// ---------------- GEMM tiling (proven: 8 warps 64x32, prefetch 2) -----------
#define BM 128
#define BN 128
#define BKB 32
#define KB  (KDIM / BKB)         // 24
#define ROWB 80
#define ARR_BYTES (128 * ROWB)
#define STAGE (2 * ARR_BYTES)
#define NSTG 4
#define SMEM_GEMM (NSTG * STAGE) // 81920

__device__ __forceinline__ void gemm_mainloop(
    const __half* __restrict__ A, const __half* __restrict__ Bw,
    int bm, int bn, uint32_t sb, int tid, int wid, int lane,
    float acc[4][4][4])
{
    const int wm = (wid & 1) * 64;
    const int wn = (wid >> 1) * 32;

    const int lrow = tid >> 2;
    const int lch  = tid & 3;
    const __half* srcs[4];
    uint32_t dsts[4];
    {
        const __half* bases[2] = { A, Bw };
        #pragma unroll
        for (int i = 0; i < 4; i++) {
            int arr = i >> 1;
            int row = (i & 1) * 64 + lrow;
            int roff = (arr == 0) ? (bm + row) : (bn + row);
            srcs[i] = bases[arr] + (size_t)roff * KDIM + lch * 8;
            dsts[i] = sb + arr * ARR_BYTES + row * ROWB + lch * 16;
        }
    }

    const uint32_t a_row  = (uint32_t)(wm + (lane & 15));
    const uint32_t a_colb = (uint32_t)(((lane >> 4) & 1) * 16);
    const uint32_t b_row4 = (uint32_t)(wn + ((lane >> 4) & 1) * 8 + (lane & 7));
    const uint32_t b_col4 = (uint32_t)(((lane >> 3) & 1) * 16);

    #pragma unroll
    for (int i = 0; i < 4; i++)
        #pragma unroll
        for (int j = 0; j < 4; j++)
            #pragma unroll
            for (int r = 0; r < 4; r++) acc[i][j][r] = 0.f;

    #pragma unroll
    for (int p = 0; p < 2; p++) {
        const uint32_t so = (uint32_t)(p * STAGE);
        const int k0 = p * BKB;
        #pragma unroll
        for (int i = 0; i < 4; i++) CP_ASYNC_CG(dsts[i] + so, srcs[i] + k0);
        CP_COMMIT();
    }

    for (int kb = 0; kb < KB; kb++) {
        const int pf = kb + 2;
        if (pf < KB) {
            const uint32_t so = (uint32_t)((pf & (NSTG - 1)) * STAGE);
            const int k0 = pf * BKB;
            #pragma unroll
            for (int i = 0; i < 4; i++) CP_ASYNC_CG(dsts[i] + so, srcs[i] + k0);
        }
        CP_COMMIT();
        CP_WAIT(2);
        __syncthreads();

        const uint32_t st = sb + (uint32_t)((kb & (NSTG - 1)) * STAGE);
        #pragma unroll
        for (int ks = 0; ks < 2; ks++) {
            const uint32_t kB = (uint32_t)(ks * 32);
            uint32_t bf[4][2];
            #pragma unroll
            for (int pr = 0; pr < 2; pr++) {
                uint32_t bo = st + ARR_BYTES + (b_row4 + pr * 16) * ROWB + kB + b_col4;
                LDMATRIX_X4(bf[2 * pr][0], bf[2 * pr][1],
                            bf[2 * pr + 1][0], bf[2 * pr + 1][1], bo);
            }
            #pragma unroll
            for (int mt = 0; mt < 4; mt++) {
                uint32_t af[4];
                uint32_t ao = st + (a_row + mt * 16) * ROWB + kB + a_colb;
                LDMATRIX_X4(af[0], af[1], af[2], af[3], ao);
                #pragma unroll
                for (int nt = 0; nt < 4; nt++)
                    MMA_F16(acc[mt][nt], af, bf[nt]);
            }
        }
    }
}

// ---------------- GEMM1: qkv with fused bias+rope+softmax+scatter ----------
#define EPS 132

__global__ __launch_bounds__(256, 2)
void mma_gemm_qkv(const __half* __restrict__ A, const __half* __restrict__ Bw,
                  const float* __restrict__ rope,
                  const float* __restrict__ q_bias, const float* __restrict__ v_bias,
                  __half* __restrict__ phiq, __half* __restrict__ phik, __half* __restrict__ vout)
{
    extern __shared__ char smem[];
    const uint32_t sb = smem_to_u32(smem);
    const int tid = threadIdx.x, wid = tid >> 5, lane = tid & 31;
    const int bm = blockIdx.y * BM, bn = blockIdx.x * BN;

    float acc[4][4][4];
    gemm_mainloop(A, Bw, bm, bn, sb, tid, wid, lane, acc);
    __syncthreads();

    float* epi = (float*)smem;
    const int wm = (wid & 1) * 64, wn = (wid >> 1) * 32;
    const int er = lane >> 2, ec = (lane & 3) * 2;
    #pragma unroll
    for (int mt = 0; mt < 4; mt++)
        #pragma unroll
        for (int nt = 0; nt < 4; nt++) {
            int r0 = wm + mt * 16 + er, c = wn + nt * 8 + ec;
            *(float2*)&epi[r0 * EPS + c]       = make_float2(acc[mt][nt][0], acc[mt][nt][1]);
            *(float2*)&epi[(r0 + 8) * EPS + c] = make_float2(acc[mt][nt][2], acc[mt][nt][3]);
        }
    __syncthreads();

    const int region = bn / C_;
    const int col0   = bn - region * C_;
    const float* bias = (region == 0) ? q_bias : (region == 2 ? v_bias : nullptr);
    __half* outbuf = (region == 0) ? phiq : (region == 1 ? phik : vout);

    const int sub    = lane >> 4;
    const int lane15 = lane & 15;
    const int g      = lane15 >> 3;
    const int dof    = (lane15 & 7) << 3;
    const int h      = (col0 >> 6) + g;

    #pragma unroll 2
    for (int rr = 0; rr < 8; rr++) {
        const int row  = wid * 16 + rr * 2 + sub;
        const int gtok = bm + row;
        const int b    = gtok >> 12;
        const int n    = gtok & (NTOK - 1);

        float4 v0 = *(float4*)&epi[row * EPS + g * 64 + dof];
        float4 v1 = *(float4*)&epi[row * EPS + g * 64 + dof + 4];
        float vals[8] = { v0.x, v0.y, v0.z, v0.w, v1.x, v1.y, v1.z, v1.w };

        if (bias) {
            #pragma unroll
            for (int j = 0; j < 8; j++) vals[j] += bias[col0 + g * 64 + dof + j];
        }

        if (region != 2) {
            if (n >= 1) {
                const float* rp = rope + (size_t)(n - 1) * (2 * D_) + dof;
                float4 s0 = *(const float4*)rp;
                float4 s1 = *(const float4*)(rp + 4);
                float4 c0 = *(const float4*)(rp + 64);
                float4 c1 = *(const float4*)(rp + 68);
                float snv[8] = { s0.x, s0.y, s0.z, s0.w, s1.x, s1.y, s1.z, s1.w };
                float csv[8] = { c0.x, c0.y, c0.z, c0.w, c1.x, c1.y, c1.z, c1.w };
                #pragma unroll
                for (int p = 0; p < 4; p++) {
                    float t0 = vals[2 * p], t1 = vals[2 * p + 1];
                    vals[2 * p]     = t0 * csv[2 * p]     - t1 * snv[2 * p];
                    vals[2 * p + 1] = t1 * csv[2 * p + 1] + t0 * snv[2 * p + 1];
                }
            }
            float m = vals[0];
            #pragma unroll
            for (int j = 1; j < 8; j++) m = fmaxf(m, vals[j]);
            #pragma unroll
            for (int o = 1; o < 8; o <<= 1)
                m = fmaxf(m, __shfl_xor_sync(0xffffffffu, m, o));
            float s = 0.f;
            #pragma unroll
            for (int j = 0; j < 8; j++) { vals[j] = expf(vals[j] - m); s += vals[j]; }
            #pragma unroll
            for (int o = 1; o < 8; o <<= 1)
                s += __shfl_xor_sync(0xffffffffu, s, o);
            float rs = 1.f / s;
            #pragma unroll
            for (int j = 0; j < 8; j++) vals[j] *= rs;
        }

        __half hv[8];
        #pragma unroll
        for (int j = 0; j < 8; j++) hv[j] = __float2half(vals[j]);
        __half* dst = outbuf + (((size_t)b * H_ + h) * NTOK + n) * D_ + dof;
        *(uint4*)dst = *(uint4*)hv;
    }
}

// ---------------- GEMM2: proj with fused LayerNorm epilogue -----------------
// out[m,n] = rstd[m]*acc - rm[m]*u[n] + tb[n]
__global__ __launch_bounds__(256, 2)
void mma_gemm_proj(const __half* __restrict__ A, const __half* __restrict__ Bw,
                   float* __restrict__ Cc, int N,
                   const float* __restrict__ rstd, const float* __restrict__ rm,
                   const float* __restrict__ u, const float* __restrict__ tb)
{
    extern __shared__ char smem[];
    const uint32_t sb = smem_to_u32(smem);
    const int tid = threadIdx.x, wid = tid >> 5, lane = tid & 31;
    const int bm = blockIdx.y * BM, bn = blockIdx.x * BN;

    float acc[4][4][4];
    gemm_mainloop(A, Bw, bm, bn, sb, tid, wid, lane, acc);

    const int wm = (wid & 1) * 64, wn = (wid >> 1) * 32;
    const int er = lane >> 2, ec = (lane & 3) * 2;
    #pragma unroll
    for (int mt = 0; mt < 4; mt++) {
        int row = bm + wm + mt * 16 + er;
        float rs0 = rstd[row],     rmm0 = rm[row];
        float rs1 = rstd[row + 8], rmm1 = rm[row + 8];
        #pragma unroll
        for (int nt = 0; nt < 4; nt++) {
            int col = bn + wn + nt * 8 + ec;
            float u0 = u[col], u1 = u[col + 1];
            float t0 = tb[col], t1 = tb[col + 1];
            *(float2*)(Cc + (size_t)row * N + col) = make_float2(
                acc[mt][nt][0] * rs0 - rmm0 * u0 + t0,
                acc[mt][nt][1] * rs0 - rmm0 * u1 + t1);
            *(float2*)(Cc + (size_t)(row + 8) * N + col) = make_float2(
                acc[mt][nt][2] * rs1 - rmm1 * u0 + t0,
                acc[mt][nt][3] * rs1 - rmm1 * u1 + t1);
        }
    }
}

// ---------------- kv via mma, 4-way split over tokens ----------------
#define KROWB 144
#define KARR  (64 * KROWB)
#define KSTG  (2 * KARR)
#define SEGTOK (NTOK / KVSEG)

__global__ __launch_bounds__(128)
void kv_mma_kernel(const __half* __restrict__ phik, const __half* __restrict__ v,
                   float* __restrict__ kvp, float* __restrict__ ksp)
{
    __shared__ char skv[2 * KSTG];
    const uint32_t sb = smem_to_u32(skv);
    const int tid = threadIdx.x, wid = tid >> 5, lane = tid & 31;
    const int bh = blockIdx.x;
    const int seg = blockIdx.y;
    const int nbase = seg * SEGTOK;

    const __half* pk = phik + (size_t)bh * NTOK * D_;
    const __half* pv = v    + (size_t)bh * NTOK * D_;

    const int wd = wid & 1, we = wid >> 1;

    const int akk = (lane & 7) + ((lane >> 4) & 1) * 8;
    const int amm = ((lane >> 3) & 1) * 8;
    const int bkk = (lane & 7) + ((lane >> 3) & 1) * 8;

    float acc[2][4][4];
    #pragma unroll
    for (int i = 0; i < 2; i++)
        #pragma unroll
        for (int j = 0; j < 4; j++)
            #pragma unroll
            for (int r = 0; r < 4; r++) acc[i][j][r] = 0.f;

    float2 ksl2 = make_float2(0.f, 0.f);
    const int dpair = tid & 31;
    const int rg = tid >> 5;

    auto fill = [&](int kb, int slot) {
        const int n0 = nbase + kb * 64;
        const uint32_t so = sb + (uint32_t)(slot * KSTG);
        #pragma unroll
        for (int i = tid; i < 1024; i += 128) {
            int arr = i >> 9;
            int r   = (i >> 3) & 63;
            int ch  = i & 7;
            const __half* src = (arr ? pv : pk) + (size_t)(n0 + r) * D_ + ch * 8;
            CP_ASYNC_CG(so + arr * KARR + r * KROWB + ch * 16, src);
        }
    };

    fill(0, 0); CP_COMMIT();

    const int NBLK = SEGTOK / 64;
    for (int kb = 0; kb < NBLK; kb++) {
        __syncthreads();
        if (kb + 1 < NBLK) { fill(kb + 1, (kb + 1) & 1); CP_COMMIT(); CP_WAIT(1); }
        else               { CP_WAIT(0); }
        __syncthreads();

        const uint32_t st = sb + (uint32_t)((kb & 1) * KSTG);

        const char* ph = skv + (kb & 1) * KSTG;
        #pragma unroll 16
        for (int r = rg * 16; r < rg * 16 + 16; r++) {
            __half2 kk = *(const __half2*)(ph + r * KROWB + dpair * 4);
            float2 kf = __half22float2(kk);
            ksl2.x += kf.x; ksl2.y += kf.y;
        }

        #pragma unroll
        for (int ks = 0; ks < 4; ks++) {
            const int k0 = ks * 16;
            uint32_t bf[4][2];
            #pragma unroll
            for (int nt = 0; nt < 4; nt++) {
                uint32_t bo = st + KARR + (k0 + bkk) * KROWB + (we * 32 + nt * 8) * 2;
                LDMATRIX_X2_T(bf[nt][0], bf[nt][1], bo);
            }
            #pragma unroll
            for (int mt = 0; mt < 2; mt++) {
                uint32_t af[4];
                uint32_t ao = st + (k0 + akk) * KROWB + (wd * 32 + mt * 16 + amm) * 2;
                LDMATRIX_X4_T(af[0], af[1], af[2], af[3], ao);
                #pragma unroll
                for (int nt = 0; nt < 4; nt++)
                    MMA_F16(acc[mt][nt], af, bf[nt]);
            }
        }
    }

    const int er = lane >> 2, ec = (lane & 3) * 2;
    float* kvb = kvp + ((size_t)seg * B_ * H_ + bh) * D_ * D_;
    #pragma unroll
    for (int mt = 0; mt < 2; mt++)
        #pragma unroll
        for (int nt = 0; nt < 4; nt++) {
            int d = wd * 32 + mt * 16 + er;
            int e = we * 32 + nt * 8 + ec;
            kvb[(e)     * D_ + d]     = acc[mt][nt][0];
            kvb[(e + 1) * D_ + d]     = acc[mt][nt][1];
            kvb[(e)     * D_ + d + 8] = acc[mt][nt][2];
            kvb[(e + 1) * D_ + d + 8] = acc[mt][nt][3];
        }

    __shared__ float kred[4][64];
    kred[rg][2 * dpair]     = ksl2.x;
    kred[rg][2 * dpair + 1] = ksl2.y;
    __syncthreads();
    if (tid < 64) {
        float s = kred[0][tid] + kred[1][tid] + kred[2][tid] + kred[3][tid];
        ksp[(seg * B_ * H_ + bh) * D_ + tid] = s;
    }
}

// ---------------- kv partial reduce -> kvT fp16 + ksum -----------------------
__global__ __launch_bounds__(256)
void kv_reduce_kernel(const float* __restrict__ kvp, const float* __restrict__ ksp,
                      __half* __restrict__ kvT, float* __restrict__ ksum)
{
    const int bh = blockIdx.x, tid = threadIdx.x;
    #pragma unroll 4
    for (int i = tid; i < D_ * D_; i += 256) {
        float s = 0.f;
        #pragma unroll
        for (int sg = 0; sg < KVSEG; sg++)
            s += kvp[((size_t)sg * B_ * H_ + bh) * D_ * D_ + i];
        kvT[(size_t)bh * D_ * D_ + i] = __float2half(s);
    }
    if (tid < D_) {
        float s = 0.f;
        #pragma unroll
        for (int sg = 0; sg < KVSEG; sg++)
            s += ksp[(sg * B_ * H_ + bh) * D_ + tid];
        ksum[bh * D_ + tid] = s;
    }
}

// ---------------- attn via mma (coalesced smem-staged epilogue) -------------
__global__ __launch_bounds__(256)
void attn_mma_kernel(const __half* __restrict__ phiq, const __half* __restrict__ kvT,
                     const float* __restrict__ ksum, __half* __restrict__ attn)
{
    __shared__ __half phq[128 * 72];
    __shared__ __half kvt[64 * 72];
    __shared__ float ksm[64];
    __shared__ float zpart[128][2];
    __shared__ float zb[128];

    const int tid = threadIdx.x, wid = tid >> 5, lane = tid & 31;
    const int bh = blockIdx.x;
    const int n0 = blockIdx.y * 128;
    const int b = bh / H_, h = bh % H_;

    const __half* pq = phiq + ((size_t)bh * NTOK + n0) * D_;
    const __half* kb = kvT + (size_t)bh * D_ * D_;

    #pragma unroll
    for (int i = tid; i < 1024; i += 256) {
        int r = i >> 3, ch = i & 7;
        *(uint4*)&phq[r * 72 + ch * 8] = *(const uint4*)(pq + (size_t)r * D_ + ch * 8);
    }
    #pragma unroll
    for (int i = tid; i < 512; i += 256) {
        int r = i >> 3, ch = i & 7;
        *(uint4*)&kvt[r * 72 + ch * 8] = *(const uint4*)(kb + (size_t)r * D_ + ch * 8);
    }
    if (tid < 64) ksm[tid] = ksum[bh * D_ + tid];
    __syncthreads();

    {
        int row = tid >> 1, hh = tid & 1;
        float z = 0.f;
        #pragma unroll 8
        for (int d = hh * 32; d < hh * 32 + 32; d++)
            z += __half2float(phq[row * 72 + d]) * ksm[d];
        zpart[row][hh] = z;
    }
    __syncthreads();
    if (tid < 128) zb[tid] = 1.f / (zpart[tid][0] + zpart[tid][1] + 1e-5f);

    const int wm2 = (wid & 3) * 32, wn2 = (wid >> 2) * 32;
    const uint32_t pq32 = smem_to_u32(phq), kv32 = smem_to_u32(kvt);
    float acc[2][4][4];
    #pragma unroll
    for (int i = 0; i < 2; i++)
        #pragma unroll
        for (int j = 0; j < 4; j++)
            #pragma unroll
            for (int r = 0; r < 4; r++) acc[i][j][r] = 0.f;

    #pragma unroll
    for (int ks = 0; ks < 4; ks++) {
        const int k0 = ks * 16;
        uint32_t bf[4][2];
        #pragma unroll
        for (int nt = 0; nt < 4; nt++) {
            uint32_t bo = kv32 + (wn2 + nt * 8 + (lane & 7)) * 144 + (k0 + ((lane >> 3) & 1) * 8) * 2;
            LDMATRIX_X2(bf[nt][0], bf[nt][1], bo);
        }
        #pragma unroll
        for (int mt = 0; mt < 2; mt++) {
            uint32_t af[4];
            uint32_t ao = pq32 + (wm2 + mt * 16 + (lane & 15)) * 144 + (k0 + ((lane >> 4) & 1) * 8) * 2;
            LDMATRIX_X4(af[0], af[1], af[2], af[3], ao);
            #pragma unroll
            for (int nt = 0; nt < 4; nt++)
                MMA_F16(acc[mt][nt], af, bf[nt]);
        }
    }
    __syncthreads();

    const int er = lane >> 2, ec = (lane & 3) * 2;
    #pragma unroll
    for (int mt = 0; mt < 2; mt++)
        #pragma unroll
        for (int nt = 0; nt < 4; nt++) {
            int row = wm2 + mt * 16 + er;
            int e   = wn2 + nt * 8 + ec;
            float rz0 = zb[row], rz1 = zb[row + 8];
            *(__half2*)&phq[row * 72 + e] =
                __floats2half2_rn(acc[mt][nt][0] * rz0, acc[mt][nt][1] * rz0);
            *(__half2*)&phq[(row + 8) * 72 + e] =
                __floats2half2_rn(acc[mt][nt][2] * rz1, acc[mt][nt][3] * rz1);
        }
    __syncthreads();

    #pragma unroll
    for (int i = tid; i < 1024; i += 256) {
        int row = i >> 3, ch = i & 7;
        __half* dst = attn + ((size_t)(b * NTOK + n0 + row)) * C_ + h * D_ + ch * 8;
        *(uint4*)dst = *(uint4*)&phq[row * 72 + ch * 8];
    }
}

// ---------------- fp32 -> fp16 ----------------
__global__ void cvt_h(const float* __restrict__ x, __half* __restrict__ y, int n4)
{
    int i = blockIdx.x * blockDim.x + threadIdx.x;
    if (i >= n4) return;
    float4 f = ((const float4*)x)[i];
    __half h[4];
    h[0] = __float2half(f.x); h[1] = __float2half(f.y);
    h[2] = __float2half(f.z); h[3] = __float2half(f.w);
    ((uint2*)y)[i] = *(uint2*)h;
}

// ---------------- proj weights with g folded: pw[n,k] = half(W[n,k]*g[k]) ---
__global__ void cvt_pw_g(const float* __restrict__ W, const float* __restrict__ g,
                         __half* __restrict__ y, int n4)
{
    int i = blockIdx.x * blockDim.x + threadIdx.x;
    if (i >= n4) return;
    int k0 = (i * 4) % KDIM;
    float4 f = ((const float4*)W)[i];
    float4 gg = *(const float4*)(g + k0);
    __half h[4];
    h[0] = __float2half(f.x * gg.x); h[1] = __float2half(f.y * gg.y);
    h[2] = __float2half(f.z * gg.z); h[3] = __float2half(f.w * gg.w);
    ((uint2*)y)[i] = *(uint2*)h;
}

// ---------------- u[n] = sum_k g[k]W[n,k]; tb[n] = sum_k b[k]W[n,k] + pb[n] --
__global__ __launch_bounds__(256)
void prep_ut(const float* __restrict__ W, const float* __restrict__ g,
             const float* __restrict__ b, const float* __restrict__ pb,
             float* __restrict__ u, float* __restrict__ tb)
{
    const int n = blockIdx.x * 8 + (threadIdx.x >> 5);
    const int lane = threadIdx.x & 31;
    const float* wr = W + (size_t)n * KDIM;
    float su = 0.f, st = 0.f;
    #pragma unroll
    for (int j = 0; j < KDIM / 32; j++) {
        int k = lane + j * 32;
        float wv = wr[k];
        su += wv * g[k];
        st += wv * b[k];
    }
    #pragma unroll
    for (int o = 16; o > 0; o >>= 1) {
        su += __shfl_xor_sync(0xffffffffu, su, o);
        st += __shfl_xor_sync(0xffffffffu, st, o);
    }
    if (lane == 0) { u[n] = su; tb[n] = st + pb[n]; }
}

// ---------------- per-row LN stats of attn: rstd, rstd*mean ------------------
__global__ __launch_bounds__(256)
void rowstat_kernel(const __half* __restrict__ x,
                    float* __restrict__ rstd, float* __restrict__ rm)
{
    const int row = blockIdx.x * 8 + (threadIdx.x >> 5);
    const int lane = threadIdx.x & 31;
    const __half* xr = x + (size_t)row * C_;
    float s = 0.f, ss = 0.f;
    #pragma unroll
    for (int j = 0; j < C_ / 64; j++) {          // 12 half2 per lane
        __half2 hv = ((const __half2*)xr)[lane + j * 32];
        float2 f = __half22float2(hv);
        s  += f.x + f.y;
        ss += f.x * f.x + f.y * f.y;
    }
    #pragma unroll
    for (int o = 16; o > 0; o >>= 1) {
        s  += __shfl_xor_sync(0xffffffffu, s,  o);
        ss += __shfl_xor_sync(0xffffffffu, ss, o);
    }
    if (lane == 0) {
        float mean = s * (1.f / C_);
        float var  = ss * (1.f / C_) - mean * mean;
        float r = rsqrtf(var + 1e-5f);
        rstd[row] = r;
        rm[row]   = r * mean;
    }
}

// ---------------- launch ------------------------------------------------------
extern "C" void kernel_launch(void* const* d_in, const int* in_sizes, int n_in,
                              void* d_out, int out_size)
{
    (void)in_sizes; (void)n_in; (void)out_size;
    const float* x      = (const float*)d_in[0];
    const float* rope   = (const float*)d_in[1];
    const float* qkv_w  = (const float*)d_in[2];
    const float* q_bias = (const float*)d_in[3];
    const float* v_bias = (const float*)d_in[4];
    const float* norm_g = (const float*)d_in[5];
    const float* norm_b = (const float*)d_in[6];
    const float* proj_w = (const float*)d_in[7];
    const float* proj_b = (const float*)d_in[8];
    float* out = (float*)d_out;

    float *ksum, *kvp, *ksp, *rstd, *rm, *u, *tb;
    __half *phiq, *phik, *v, *kvT, *attn, *xh, *w, *pw;
    cudaGetSymbolAddress((void**)&phiq, g_phiq);
    cudaGetSymbolAddress((void**)&phik, g_phik);
    cudaGetSymbolAddress((void**)&v,    g_v);
    cudaGetSymbolAddress((void**)&kvT,  g_kvT);
    cudaGetSymbolAddress((void**)&kvp,  g_kvp);
    cudaGetSymbolAddress((void**)&ksum, g_ksum);
    cudaGetSymbolAddress((void**)&ksp,  g_ksp);
    cudaGetSymbolAddress((void**)&attn, g_attn);
    cudaGetSymbolAddress((void**)&xh,   g_xh);
    cudaGetSymbolAddress((void**)&w,    g_w);
    cudaGetSymbolAddress((void**)&pw,   g_pw);
    cudaGetSymbolAddress((void**)&rstd, g_rstd);
    cudaGetSymbolAddress((void**)&rm,   g_rm);
    cudaGetSymbolAddress((void**)&u,    g_u);
    cudaGetSymbolAddress((void**)&tb,   g_tb);

    cudaFuncSetAttribute(mma_gemm_qkv,  cudaFuncAttributeMaxDynamicSharedMemorySize, SMEM_GEMM);
    cudaFuncSetAttribute(mma_gemm_proj, cudaFuncAttributeMaxDynamicSharedMemorySize, SMEM_GEMM);

    // 0) conversions + LN/proj prep
    {
        int n4 = (M_ * KDIM) / 4;
        cvt_h<<<(n4 + 255) / 256, 256>>>(x, xh, n4);
        n4 = (QKVN * KDIM) / 4;
        cvt_h<<<(n4 + 255) / 256, 256>>>(qkv_w, w, n4);
        n4 = (C_ * KDIM) / 4;
        cvt_pw_g<<<(n4 + 255) / 256, 256>>>(proj_w, norm_g, pw, n4);
        prep_ut<<<C_ / 8, 256>>>(proj_w, norm_g, norm_b, proj_b, u, tb);
    }

    // 1) fused qkv GEMM + bias + rope + softmax + head-scatter (fp16 out)
    mma_gemm_qkv<<<dim3(QKVN / BN, M_ / BM), 256, SMEM_GEMM>>>(
        xh, w, rope, q_bias, v_bias, phiq, phik, v);

    // 2) kv partials via tensor cores, then reduce
    kv_mma_kernel<<<dim3(B_ * H_, KVSEG), 128>>>(phik, v, kvp, ksp);
    kv_reduce_kernel<<<B_ * H_, 256>>>(kvp, ksp, kvT, ksum);

    // 3) attention output via tensor cores (coalesced stores)
    attn_mma_kernel<<<dim3(B_ * H_, NTOK / 128), 256>>>(phiq, kvT, ksum, attn);

    // 4) per-row LN stats of attn
    rowstat_kernel<<<M_ / 8, 256>>>(attn, rstd, rm);

    // 5) out = LN(attn) @ (g*proj_w)^T + proj_b  — LN folded into epilogue
    mma_gemm_proj<<<dim3(C_ / BN, M_ / BM), 256, SMEM_GEMM>>>(
        attn, pw, out, C_, rstd, rm, u, tb);
}

// round 17
// speedup vs baseline: 1.5917x; 1.0064x over previous
#include <cuda_runtime.h>
#include <cuda_fp16.h>
#include <cstdint>

// ---------------- problem constants ----------------
#define B_    8
#define NTOK  4096
#define C_    768
#define H_    12
#define D_    64
#define M_    (B_ * NTOK)     // 32768
#define QKVN  (3 * C_)        // 2304
#define KDIM  768
#define KVSEG 4

// ---------------- scratch (device globals) ----------------
__device__ __half g_phiq[(size_t)B_ * H_ * NTOK * D_];
__device__ __half g_phik[(size_t)B_ * H_ * NTOK * D_];
__device__ __half g_v   [(size_t)B_ * H_ * NTOK * D_];
__device__ __half g_kvT [B_ * H_ * D_ * D_];
__device__ float  g_kvp [KVSEG * B_ * H_ * D_ * D_];
__device__ float  g_ksum[B_ * H_ * D_];
__device__ float  g_ksp [KVSEG * B_ * H_ * D_];
__device__ __half g_attn[(size_t)M_ * C_];

__device__ __half g_xh [(size_t)M_ * KDIM];
__device__ __half g_w  [(size_t)QKVN * KDIM];
__device__ __half g_pw [(size_t)C_ * KDIM];    // g-folded proj weights
__device__ float  g_rstd[M_];
__device__ float  g_rm [M_];
__device__ float  g_u  [C_];
__device__ float  g_tb [C_];
__device__ float  g_sps[H_ * M_];              // per-head row-sum partials
__device__ float  g_sss[H_ * M_];              // per-head row-sumsq partials

// ---------------- low-level helpers ----------------
__device__ __forceinline__ uint32_t smem_to_u32(const void* p) {
    uint32_t a;
    asm("{ .reg .u64 t; cvta.to.shared.u64 t, %1; cvt.u32.u64 %0, t; }"
        : "=r"(a) : "l"(p));
    return a;
}

#define CP_ASYNC_CG(dst, src) \
    asm volatile("cp.async.cg.shared.global [%0], [%1], 16;" :: "r"(dst), "l"(src))
#define CP_COMMIT()  asm volatile("cp.async.commit_group;" ::: "memory")
#define CP_WAIT(N)   asm volatile("cp.async.wait_group %0;" :: "n"(N) : "memory")

#define LDMATRIX_X4(r0, r1, r2, r3, addr) \
    asm volatile("ldmatrix.sync.aligned.m8n8.x4.shared.b16 {%0,%1,%2,%3}, [%4];" \
        : "=r"(r0), "=r"(r1), "=r"(r2), "=r"(r3) : "r"(addr))
#define LDMATRIX_X2(r0, r1, addr) \
    asm volatile("ldmatrix.sync.aligned.m8n8.x2.shared.b16 {%0,%1}, [%2];" \
        : "=r"(r0), "=r"(r1) : "r"(addr))
#define LDMATRIX_X4_T(r0, r1, r2, r3, addr) \
    asm volatile("ldmatrix.sync.aligned.m8n8.x4.trans.shared.b16 {%0,%1,%2,%3}, [%4];" \
        : "=r"(r0), "=r"(r1), "=r"(r2), "=r"(r3) : "r"(addr))
#define LDMATRIX_X2_T(r0, r1, addr) \
    asm volatile("ldmatrix.sync.aligned.m8n8.x2.trans.shared.b16 {%0,%1}, [%2];" \
        : "=r"(r0), "=r"(r1) : "r"(addr))

#define MMA_F16(d, a, b) \
    asm volatile("mma.sync.aligned.m16n8k16.row.col.f32.f16.f16.f32 " \
        "{%0,%1,%2,%3}, {%4,%5,%6,%7}, {%8,%9}, {%0,%1,%2,%3};" \
        : "+f"((d)[0]), "+f"((d)[1]), "+f"((d)[2]), "+f"((d)[3]) \
        : "r"((a)[0]), "r"((a)[1]), "r"((a)[2]), "r"((a)[3]), \
          "r"((b)[0]), "r"((b)[1]))

// ---------------- GEMM tiling (proven: 8 warps 64x32, prefetch 2) -----------
#define BM 128
#define BN 128
#define BKB 32
#define KB  (KDIM / BKB)
#define ROWB 80
#define ARR_BYTES (128 * ROWB)
#define STAGE (2 * ARR_BYTES)
#define NSTG 4
#define SMEM_GEMM (NSTG * STAGE)

__device__ __forceinline__ void gemm_mainloop(
    const __half* __restrict__ A, const __half* __restrict__ Bw,
    int bm, int bn, uint32_t sb, int tid, int wid, int lane,
    float acc[4][4][4])
{
    const int wm = (wid & 1) * 64;
    const int wn = (wid >> 1) * 32;

    const int lrow = tid >> 2;
    const int lch  = tid & 3;
    const __half* srcs[4];
    uint32_t dsts[4];
    {
        const __half* bases[2] = { A, Bw };
        #pragma unroll
        for (int i = 0; i < 4; i++) {
            int arr = i >> 1;
            int row = (i & 1) * 64 + lrow;
            int roff = (arr == 0) ? (bm + row) : (bn + row);
            srcs[i] = bases[arr] + (size_t)roff * KDIM + lch * 8;
            dsts[i] = sb + arr * ARR_BYTES + row * ROWB + lch * 16;
        }
    }

    const uint32_t a_row  = (uint32_t)(wm + (lane & 15));
    const uint32_t a_colb = (uint32_t)(((lane >> 4) & 1) * 16);
    const uint32_t b_row4 = (uint32_t)(wn + ((lane >> 4) & 1) * 8 + (lane & 7));
    const uint32_t b_col4 = (uint32_t)(((lane >> 3) & 1) * 16);

    #pragma unroll
    for (int i = 0; i < 4; i++)
        #pragma unroll
        for (int j = 0; j < 4; j++)
            #pragma unroll
            for (int r = 0; r < 4; r++) acc[i][j][r] = 0.f;

    #pragma unroll
    for (int p = 0; p < 2; p++) {
        const uint32_t so = (uint32_t)(p * STAGE);
        const int k0 = p * BKB;
        #pragma unroll
        for (int i = 0; i < 4; i++) CP_ASYNC_CG(dsts[i] + so, srcs[i] + k0);
        CP_COMMIT();
    }

    for (int kb = 0; kb < KB; kb++) {
        const int pf = kb + 2;
        if (pf < KB) {
            const uint32_t so = (uint32_t)((pf & (NSTG - 1)) * STAGE);
            const int k0 = pf * BKB;
            #pragma unroll
            for (int i = 0; i < 4; i++) CP_ASYNC_CG(dsts[i] + so, srcs[i] + k0);
        }
        CP_COMMIT();
        CP_WAIT(2);
        __syncthreads();

        const uint32_t st = sb + (uint32_t)((kb & (NSTG - 1)) * STAGE);
        #pragma unroll
        for (int ks = 0; ks < 2; ks++) {
            const uint32_t kB = (uint32_t)(ks * 32);
            uint32_t bf[4][2];
            #pragma unroll
            for (int pr = 0; pr < 2; pr++) {
                uint32_t bo = st + ARR_BYTES + (b_row4 + pr * 16) * ROWB + kB + b_col4;
                LDMATRIX_X4(bf[2 * pr][0], bf[2 * pr][1],
                            bf[2 * pr + 1][0], bf[2 * pr + 1][1], bo);
            }
            #pragma unroll
            for (int mt = 0; mt < 4; mt++) {
                uint32_t af[4];
                uint32_t ao = st + (a_row + mt * 16) * ROWB + kB + a_colb;
                LDMATRIX_X4(af[0], af[1], af[2], af[3], ao);
                #pragma unroll
                for (int nt = 0; nt < 4; nt++)
                    MMA_F16(acc[mt][nt], af, bf[nt]);
            }
        }
    }
}

// ---------------- GEMM1: qkv with fused bias+rope+softmax+scatter ----------
#define EPS 132

__global__ __launch_bounds__(256, 2)
void mma_gemm_qkv(const __half* __restrict__ A, const __half* __restrict__ Bw,
                  const float* __restrict__ rope,
                  const float* __restrict__ q_bias, const float* __restrict__ v_bias,
                  __half* __restrict__ phiq, __half* __restrict__ phik, __half* __restrict__ vout)
{
    extern __shared__ char smem[];
    const uint32_t sb = smem_to_u32(smem);
    const int tid = threadIdx.x, wid = tid >> 5, lane = tid & 31;
    const int bm = blockIdx.y * BM, bn = blockIdx.x * BN;

    float acc[4][4][4];
    gemm_mainloop(A, Bw, bm, bn, sb, tid, wid, lane, acc);
    __syncthreads();

    float* epi = (float*)smem;
    const int wm = (wid & 1) * 64, wn = (wid >> 1) * 32;
    const int er = lane >> 2, ec = (lane & 3) * 2;
    #pragma unroll
    for (int mt = 0; mt < 4; mt++)
        #pragma unroll
        for (int nt = 0; nt < 4; nt++) {
            int r0 = wm + mt * 16 + er, c = wn + nt * 8 + ec;
            *(float2*)&epi[r0 * EPS + c]       = make_float2(acc[mt][nt][0], acc[mt][nt][1]);
            *(float2*)&epi[(r0 + 8) * EPS + c] = make_float2(acc[mt][nt][2], acc[mt][nt][3]);
        }
    __syncthreads();

    const int region = bn / C_;
    const int col0   = bn - region * C_;
    const float* bias = (region == 0) ? q_bias : (region == 2 ? v_bias : nullptr);
    __half* outbuf = (region == 0) ? phiq : (region == 1 ? phik : vout);

    const int sub    = lane >> 4;
    const int lane15 = lane & 15;
    const int g      = lane15 >> 3;
    const int dof    = (lane15 & 7) << 3;
    const int h      = (col0 >> 6) + g;

    #pragma unroll 2
    for (int rr = 0; rr < 8; rr++) {
        const int row  = wid * 16 + rr * 2 + sub;
        const int gtok = bm + row;
        const int b    = gtok >> 12;
        const int n    = gtok & (NTOK - 1);

        float4 v0 = *(float4*)&epi[row * EPS + g * 64 + dof];
        float4 v1 = *(float4*)&epi[row * EPS + g * 64 + dof + 4];
        float vals[8] = { v0.x, v0.y, v0.z, v0.w, v1.x, v1.y, v1.z, v1.w };

        if (bias) {
            #pragma unroll
            for (int j = 0; j < 8; j++) vals[j] += bias[col0 + g * 64 + dof + j];
        }

        if (region != 2) {
            if (n >= 1) {
                const float* rp = rope + (size_t)(n - 1) * (2 * D_) + dof;
                float4 s0 = *(const float4*)rp;
                float4 s1 = *(const float4*)(rp + 4);
                float4 c0 = *(const float4*)(rp + 64);
                float4 c1 = *(const float4*)(rp + 68);
                float snv[8] = { s0.x, s0.y, s0.z, s0.w, s1.x, s1.y, s1.z, s1.w };
                float csv[8] = { c0.x, c0.y, c0.z, c0.w, c1.x, c1.y, c1.z, c1.w };
                #pragma unroll
                for (int p = 0; p < 4; p++) {
                    float t0 = vals[2 * p], t1 = vals[2 * p + 1];
                    vals[2 * p]     = t0 * csv[2 * p]     - t1 * snv[2 * p];
                    vals[2 * p + 1] = t1 * csv[2 * p + 1] + t0 * snv[2 * p + 1];
                }
            }
            float m = vals[0];
            #pragma unroll
            for (int j = 1; j < 8; j++) m = fmaxf(m, vals[j]);
            #pragma unroll
            for (int o = 1; o < 8; o <<= 1)
                m = fmaxf(m, __shfl_xor_sync(0xffffffffu, m, o));
            float s = 0.f;
            #pragma unroll
            for (int j = 0; j < 8; j++) { vals[j] = expf(vals[j] - m); s += vals[j]; }
            #pragma unroll
            for (int o = 1; o < 8; o <<= 1)
                s += __shfl_xor_sync(0xffffffffu, s, o);
            float rs = 1.f / s;
            #pragma unroll
            for (int j = 0; j < 8; j++) vals[j] *= rs;
        }

        __half hv[8];
        #pragma unroll
        for (int j = 0; j < 8; j++) hv[j] = __float2half(vals[j]);
        __half* dst = outbuf + (((size_t)b * H_ + h) * NTOK + n) * D_ + dof;
        *(uint4*)dst = *(uint4*)hv;
    }
}

// ---------------- GEMM2: proj with fused LayerNorm epilogue -----------------
__global__ __launch_bounds__(256, 2)
void mma_gemm_proj(const __half* __restrict__ A, const __half* __restrict__ Bw,
                   float* __restrict__ Cc, int N,
                   const float* __restrict__ rstd, const float* __restrict__ rm,
                   const float* __restrict__ u, const float* __restrict__ tb)
{
    extern __shared__ char smem[];
    const uint32_t sb = smem_to_u32(smem);
    const int tid = threadIdx.x, wid = tid >> 5, lane = tid & 31;
    const int bm = blockIdx.y * BM, bn = blockIdx.x * BN;

    float acc[4][4][4];
    gemm_mainloop(A, Bw, bm, bn, sb, tid, wid, lane, acc);

    const int wm = (wid & 1) * 64, wn = (wid >> 1) * 32;
    const int er = lane >> 2, ec = (lane & 3) * 2;
    #pragma unroll
    for (int mt = 0; mt < 4; mt++) {
        int row = bm + wm + mt * 16 + er;
        float rs0 = rstd[row],     rmm0 = rm[row];
        float rs1 = rstd[row + 8], rmm1 = rm[row + 8];
        #pragma unroll
        for (int nt = 0; nt < 4; nt++) {
            int col = bn + wn + nt * 8 + ec;
            float u0 = u[col], u1 = u[col + 1];
            float t0 = tb[col], t1 = tb[col + 1];
            *(float2*)(Cc + (size_t)row * N + col) = make_float2(
                acc[mt][nt][0] * rs0 - rmm0 * u0 + t0,
                acc[mt][nt][1] * rs0 - rmm0 * u1 + t1);
            *(float2*)(Cc + (size_t)(row + 8) * N + col) = make_float2(
                acc[mt][nt][2] * rs1 - rmm1 * u0 + t0,
                acc[mt][nt][3] * rs1 - rmm1 * u1 + t1);
        }
    }
}

// ---------------- kv via mma, 4-way split over tokens ----------------
#define KROWB 144
#define KARR  (64 * KROWB)
#define KSTG  (2 * KARR)
#define SEGTOK (NTOK / KVSEG)

__global__ __launch_bounds__(128)
void kv_mma_kernel(const __half* __restrict__ phik, const __half* __restrict__ v,
                   float* __restrict__ kvp, float* __restrict__ ksp)
{
    __shared__ char skv[2 * KSTG];
    const uint32_t sb = smem_to_u32(skv);
    const int tid = threadIdx.x, wid = tid >> 5, lane = tid & 31;
    const int bh = blockIdx.x;
    const int seg = blockIdx.y;
    const int nbase = seg * SEGTOK;

    const __half* pk = phik + (size_t)bh * NTOK * D_;
    const __half* pv = v    + (size_t)bh * NTOK * D_;

    const int wd = wid & 1, we = wid >> 1;

    const int akk = (lane & 7) + ((lane >> 4) & 1) * 8;
    const int amm = ((lane >> 3) & 1) * 8;
    const int bkk = (lane & 7) + ((lane >> 3) & 1) * 8;

    float acc[2][4][4];
    #pragma unroll
    for (int i = 0; i < 2; i++)
        #pragma unroll
        for (int j = 0; j < 4; j++)
            #pragma unroll
            for (int r = 0; r < 4; r++) acc[i][j][r] = 0.f;

    float2 ksl2 = make_float2(0.f, 0.f);
    const int dpair = tid & 31;
    const int rg = tid >> 5;

    auto fill = [&](int kb, int slot) {
        const int n0 = nbase + kb * 64;
        const uint32_t so = sb + (uint32_t)(slot * KSTG);
        #pragma unroll
        for (int i = tid; i < 1024; i += 128) {
            int arr = i >> 9;
            int r   = (i >> 3) & 63;
            int ch  = i & 7;
            const __half* src = (arr ? pv : pk) + (size_t)(n0 + r) * D_ + ch * 8;
            CP_ASYNC_CG(so + arr * KARR + r * KROWB + ch * 16, src);
        }
    };

    fill(0, 0); CP_COMMIT();

    const int NBLK = SEGTOK / 64;
    for (int kb = 0; kb < NBLK; kb++) {
        __syncthreads();
        if (kb + 1 < NBLK) { fill(kb + 1, (kb + 1) & 1); CP_COMMIT(); CP_WAIT(1); }
        else               { CP_WAIT(0); }
        __syncthreads();

        const uint32_t st = sb + (uint32_t)((kb & 1) * KSTG);

        const char* ph = skv + (kb & 1) * KSTG;
        #pragma unroll 16
        for (int r = rg * 16; r < rg * 16 + 16; r++) {
            __half2 kk = *(const __half2*)(ph + r * KROWB + dpair * 4);
            float2 kf = __half22float2(kk);
            ksl2.x += kf.x; ksl2.y += kf.y;
        }

        #pragma unroll
        for (int ks = 0; ks < 4; ks++) {
            const int k0 = ks * 16;
            uint32_t bf[4][2];
            #pragma unroll
            for (int nt = 0; nt < 4; nt++) {
                uint32_t bo = st + KARR + (k0 + bkk) * KROWB + (we * 32 + nt * 8) * 2;
                LDMATRIX_X2_T(bf[nt][0], bf[nt][1], bo);
            }
            #pragma unroll
            for (int mt = 0; mt < 2; mt++) {
                uint32_t af[4];
                uint32_t ao = st + (k0 + akk) * KROWB + (wd * 32 + mt * 16 + amm) * 2;
                LDMATRIX_X4_T(af[0], af[1], af[2], af[3], ao);
                #pragma unroll
                for (int nt = 0; nt < 4; nt++)
                    MMA_F16(acc[mt][nt], af, bf[nt]);
            }
        }
    }

    const int er = lane >> 2, ec = (lane & 3) * 2;
    float* kvb = kvp + ((size_t)seg * B_ * H_ + bh) * D_ * D_;
    #pragma unroll
    for (int mt = 0; mt < 2; mt++)
        #pragma unroll
        for (int nt = 0; nt < 4; nt++) {
            int d = wd * 32 + mt * 16 + er;
            int e = we * 32 + nt * 8 + ec;
            kvb[(e)     * D_ + d]     = acc[mt][nt][0];
            kvb[(e + 1) * D_ + d]     = acc[mt][nt][1];
            kvb[(e)     * D_ + d + 8] = acc[mt][nt][2];
            kvb[(e + 1) * D_ + d + 8] = acc[mt][nt][3];
        }

    __shared__ float kred[4][64];
    kred[rg][2 * dpair]     = ksl2.x;
    kred[rg][2 * dpair + 1] = ksl2.y;
    __syncthreads();
    if (tid < 64) {
        float s = kred[0][tid] + kred[1][tid] + kred[2][tid] + kred[3][tid];
        ksp[(seg * B_ * H_ + bh) * D_ + tid] = s;
    }
}

// ---------------- kv partial reduce -> kvT fp16 + ksum -----------------------
__global__ __launch_bounds__(256)
void kv_reduce_kernel(const float* __restrict__ kvp, const float* __restrict__ ksp,
                      __half* __restrict__ kvT, float* __restrict__ ksum)
{
    const int bh = blockIdx.x, tid = threadIdx.x;
    #pragma unroll 4
    for (int i = tid; i < D_ * D_; i += 256) {
        float s = 0.f;
        #pragma unroll
        for (int sg = 0; sg < KVSEG; sg++)
            s += kvp[((size_t)sg * B_ * H_ + bh) * D_ * D_ + i];
        kvT[(size_t)bh * D_ * D_ + i] = __float2half(s);
    }
    if (tid < D_) {
        float s = 0.f;
        #pragma unroll
        for (int sg = 0; sg < KVSEG; sg++)
            s += ksp[(sg * B_ * H_ + bh) * D_ + tid];
        ksum[bh * D_ + tid] = s;
    }
}

// ---------------- attn via mma + fused LN row-stat partials ------------------
__global__ __launch_bounds__(256)
void attn_mma_kernel(const __half* __restrict__ phiq, const __half* __restrict__ kvT,
                     const float* __restrict__ ksum, __half* __restrict__ attn,
                     float* __restrict__ sps, float* __restrict__ sss)
{
    __shared__ __half phq[128 * 72];
    __shared__ __half kvt[64 * 72];
    __shared__ float ksm[64];
    __shared__ float zpart[128][2];
    __shared__ float zb[128];

    const int tid = threadIdx.x, wid = tid >> 5, lane = tid & 31;
    const int bh = blockIdx.x;
    const int n0 = blockIdx.y * 128;
    const int b = bh / H_, h = bh % H_;

    const __half* pq = phiq + ((size_t)bh * NTOK + n0) * D_;
    const __half* kb = kvT + (size_t)bh * D_ * D_;

    #pragma unroll
    for (int i = tid; i < 1024; i += 256) {
        int r = i >> 3, ch = i & 7;
        *(uint4*)&phq[r * 72 + ch * 8] = *(const uint4*)(pq + (size_t)r * D_ + ch * 8);
    }
    #pragma unroll
    for (int i = tid; i < 512; i += 256) {
        int r = i >> 3, ch = i & 7;
        *(uint4*)&kvt[r * 72 + ch * 8] = *(const uint4*)(kb + (size_t)r * D_ + ch * 8);
    }
    if (tid < 64) ksm[tid] = ksum[bh * D_ + tid];
    __syncthreads();

    {
        int row = tid >> 1, hh = tid & 1;
        float z = 0.f;
        #pragma unroll 8
        for (int d = hh * 32; d < hh * 32 + 32; d++)
            z += __half2float(phq[row * 72 + d]) * ksm[d];
        zpart[row][hh] = z;
    }
    __syncthreads();
    if (tid < 128) zb[tid] = 1.f / (zpart[tid][0] + zpart[tid][1] + 1e-5f);

    const int wm2 = (wid & 3) * 32, wn2 = (wid >> 2) * 32;
    const uint32_t pq32 = smem_to_u32(phq), kv32 = smem_to_u32(kvt);
    float acc[2][4][4];
    #pragma unroll
    for (int i = 0; i < 2; i++)
        #pragma unroll
        for (int j = 0; j < 4; j++)
            #pragma unroll
            for (int r = 0; r < 4; r++) acc[i][j][r] = 0.f;

    #pragma unroll
    for (int ks = 0; ks < 4; ks++) {
        const int k0 = ks * 16;
        uint32_t bf[4][2];
        #pragma unroll
        for (int nt = 0; nt < 4; nt++) {
            uint32_t bo = kv32 + (wn2 + nt * 8 + (lane & 7)) * 144 + (k0 + ((lane >> 3) & 1) * 8) * 2;
            LDMATRIX_X2(bf[nt][0], bf[nt][1], bo);
        }
        #pragma unroll
        for (int mt = 0; mt < 2; mt++) {
            uint32_t af[4];
            uint32_t ao = pq32 + (wm2 + mt * 16 + (lane & 15)) * 144 + (k0 + ((lane >> 4) & 1) * 8) * 2;
            LDMATRIX_X4(af[0], af[1], af[2], af[3], ao);
            #pragma unroll
            for (int nt = 0; nt < 4; nt++)
                MMA_F16(acc[mt][nt], af, bf[nt]);
        }
    }
    __syncthreads();

    const int er = lane >> 2, ec = (lane & 3) * 2;
    #pragma unroll
    for (int mt = 0; mt < 2; mt++)
        #pragma unroll
        for (int nt = 0; nt < 4; nt++) {
            int row = wm2 + mt * 16 + er;
            int e   = wn2 + nt * 8 + ec;
            float rz0 = zb[row], rz1 = zb[row + 8];
            *(__half2*)&phq[row * 72 + e] =
                __floats2half2_rn(acc[mt][nt][0] * rz0, acc[mt][nt][1] * rz0);
            *(__half2*)&phq[(row + 8) * 72 + e] =
                __floats2half2_rn(acc[mt][nt][2] * rz1, acc[mt][nt][3] * rz1);
        }
    __syncthreads();

    // coalesced stores + per-row LN partials over this head's 64 columns
    #pragma unroll
    for (int i = tid; i < 1024; i += 256) {
        int row = i >> 3, ch = i & 7;
        __half* dst = attn + ((size_t)(b * NTOK + n0 + row)) * C_ + h * D_ + ch * 8;
        *(uint4*)dst = *(uint4*)&phq[row * 72 + ch * 8];
    }
    {
        int row = tid >> 1, hh = tid & 1;
        const __half2* pr = (const __half2*)&phq[row * 72 + hh * 32];
        float s = 0.f, ss = 0.f;
        #pragma unroll
        for (int j = 0; j < 16; j++) {
            float2 f = __half22float2(pr[j]);
            s  += f.x + f.y;
            ss += f.x * f.x + f.y * f.y;
        }
        s  += __shfl_xor_sync(0xffffffffu, s,  1);
        ss += __shfl_xor_sync(0xffffffffu, ss, 1);
        if (hh == 0) {
            int m = b * NTOK + n0 + row;
            sps[h * M_ + m] = s;
            sss[h * M_ + m] = ss;
        }
    }
}

// ---------------- finalize LN stats: reduce 12 head-partials per row ---------
__global__ __launch_bounds__(256)
void stat_final(const float* __restrict__ sps, const float* __restrict__ sss,
                float* __restrict__ rstd, float* __restrict__ rm)
{
    int m = blockIdx.x * 256 + threadIdx.x;
    float s = 0.f, ss = 0.f;
    #pragma unroll
    for (int h = 0; h < H_; h++) {
        s  += sps[h * M_ + m];
        ss += sss[h * M_ + m];
    }
    float mean = s * (1.f / C_);
    float var  = ss * (1.f / C_) - mean * mean;
    float r = rsqrtf(var + 1e-5f);
    rstd[m] = r;
    rm[m]   = r * mean;
}

// ---------------- fp32 -> fp16 ----------------
__global__ void cvt_h(const float* __restrict__ x, __half* __restrict__ y, int n4)
{
    int i = blockIdx.x * blockDim.x + threadIdx.x;
    if (i >= n4) return;
    float4 f = ((const float4*)x)[i];
    __half h[4];
    h[0] = __float2half(f.x); h[1] = __float2half(f.y);
    h[2] = __float2half(f.z); h[3] = __float2half(f.w);
    ((uint2*)y)[i] = *(uint2*)h;
}

// ---------------- proj prep: pw (g-folded fp16), u, tb in ONE pass -----------
__global__ __launch_bounds__(256)
void prep_proj(const float* __restrict__ W, const float* __restrict__ g,
               const float* __restrict__ b, const float* __restrict__ pb,
               __half* __restrict__ pw, float* __restrict__ u, float* __restrict__ tb)
{
    const int n = blockIdx.x;
    const int tid = threadIdx.x;
    const float* wr = W + (size_t)n * KDIM;
    float su = 0.f, st = 0.f;
    #pragma unroll
    for (int j = 0; j < KDIM / 256; j++) {
        int k = tid + j * 256;
        float wv = wr[k], gv = g[k];
        su += wv * gv;
        st += wv * b[k];
        pw[(size_t)n * KDIM + k] = __float2half(wv * gv);
    }
    #pragma unroll
    for (int o = 16; o > 0; o >>= 1) {
        su += __shfl_xor_sync(0xffffffffu, su, o);
        st += __shfl_xor_sync(0xffffffffu, st, o);
    }
    __shared__ float wsu[8], wst[8];
    int warp = tid >> 5, lane = tid & 31;
    if (lane == 0) { wsu[warp] = su; wst[warp] = st; }
    __syncthreads();
    if (tid == 0) {
        float tu = 0.f, tt = 0.f;
        #pragma unroll
        for (int i = 0; i < 8; i++) { tu += wsu[i]; tt += wst[i]; }
        u[n] = tu;
        tb[n] = tt + pb[n];
    }
}

// ---------------- launch ------------------------------------------------------
extern "C" void kernel_launch(void* const* d_in, const int* in_sizes, int n_in,
                              void* d_out, int out_size)
{
    (void)in_sizes; (void)n_in; (void)out_size;
    const float* x      = (const float*)d_in[0];
    const float* rope   = (const float*)d_in[1];
    const float* qkv_w  = (const float*)d_in[2];
    const float* q_bias = (const float*)d_in[3];
    const float* v_bias = (const float*)d_in[4];
    const float* norm_g = (const float*)d_in[5];
    const float* norm_b = (const float*)d_in[6];
    const float* proj_w = (const float*)d_in[7];
    const float* proj_b = (const float*)d_in[8];
    float* out = (float*)d_out;

    float *ksum, *kvp, *ksp, *rstd, *rm, *u, *tb, *sps, *sss;
    __half *phiq, *phik, *v, *kvT, *attn, *xh, *w, *pw;
    cudaGetSymbolAddress((void**)&phiq, g_phiq);
    cudaGetSymbolAddress((void**)&phik, g_phik);
    cudaGetSymbolAddress((void**)&v,    g_v);
    cudaGetSymbolAddress((void**)&kvT,  g_kvT);
    cudaGetSymbolAddress((void**)&kvp,  g_kvp);
    cudaGetSymbolAddress((void**)&ksum, g_ksum);
    cudaGetSymbolAddress((void**)&ksp,  g_ksp);
    cudaGetSymbolAddress((void**)&attn, g_attn);
    cudaGetSymbolAddress((void**)&xh,   g_xh);
    cudaGetSymbolAddress((void**)&w,    g_w);
    cudaGetSymbolAddress((void**)&pw,   g_pw);
    cudaGetSymbolAddress((void**)&rstd, g_rstd);
    cudaGetSymbolAddress((void**)&rm,   g_rm);
    cudaGetSymbolAddress((void**)&u,    g_u);
    cudaGetSymbolAddress((void**)&tb,   g_tb);
    cudaGetSymbolAddress((void**)&sps,  g_sps);
    cudaGetSymbolAddress((void**)&sss,  g_sss);

    cudaFuncSetAttribute(mma_gemm_qkv,  cudaFuncAttributeMaxDynamicSharedMemorySize, SMEM_GEMM);
    cudaFuncSetAttribute(mma_gemm_proj, cudaFuncAttributeMaxDynamicSharedMemorySize, SMEM_GEMM);

    // 0) conversions + proj prep (single pass over proj_w)
    {
        int n4 = (M_ * KDIM) / 4;
        cvt_h<<<(n4 + 255) / 256, 256>>>(x, xh, n4);
        n4 = (QKVN * KDIM) / 4;
        cvt_h<<<(n4 + 255) / 256, 256>>>(qkv_w, w, n4);
        prep_proj<<<C_, 256>>>(proj_w, norm_g, norm_b, proj_b, pw, u, tb);
    }

    // 1) fused qkv GEMM + bias + rope + softmax + head-scatter (fp16 out)
    mma_gemm_qkv<<<dim3(QKVN / BN, M_ / BM), 256, SMEM_GEMM>>>(
        xh, w, rope, q_bias, v_bias, phiq, phik, v);

    // 2) kv partials via tensor cores, then reduce
    kv_mma_kernel<<<dim3(B_ * H_, KVSEG), 128>>>(phik, v, kvp, ksp);
    kv_reduce_kernel<<<B_ * H_, 256>>>(kvp, ksp, kvT, ksum);

    // 3) attention output via tensor cores + fused LN row-stat partials
    attn_mma_kernel<<<dim3(B_ * H_, NTOK / 128), 256>>>(phiq, kvT, ksum, attn, sps, sss);

    // 4) finalize LN stats (tiny)
    stat_final<<<M_ / 256, 256>>>(sps, sss, rstd, rm);

    // 5) out = LN(attn) @ (g*proj_w)^T + proj_b — LN folded into epilogue
    mma_gemm_proj<<<dim3(C_ / BN, M_ / BM), 256, SMEM_GEMM>>>(
        attn, pw, out, C_, rstd, rm, u, tb);
}